// round 11
// baseline (speedup 1.0000x reference)
#include <cuda_runtime.h>
#include <cuda_fp16.h>
#include <cstdint>

// Problem constants
#define N_NODES 100000
#define E_EDGES 1000000
#define H_DIMC  124
#define XDIM    128
#define HIDDEN  256
#define CTOT    512     // A (256) || B (256)
#define KSP     256     // split-K: [hi | lo]

// ---------------------------------------------------------------------------
// Static device scratch
// ---------------------------------------------------------------------------
__device__ __half g_Xs[(size_t)N_NODES * KSP];   // [N,256] fp16 split X (51MB)
__device__ __half g_Ws[(size_t)KSP * CTOT];      // [256,512] fp16: rows k and 128+k = hi(Wg[k])
__device__ __half g_Ch[(size_t)N_NODES * CTOT];  // [N,512] fp16 = [A|B], b1 folded into A
__device__ int    g_idx64;

// ---------------------------------------------------------------------------
// PTX helpers
// ---------------------------------------------------------------------------
__device__ __forceinline__ uint32_t smem_u32(const void* p) {
    return (uint32_t)__cvta_generic_to_shared(p);
}
__device__ __forceinline__ void ldsm_x4(uint32_t (&r)[4], uint32_t addr) {
    asm volatile("ldmatrix.sync.aligned.m8n8.x4.shared.b16 {%0,%1,%2,%3}, [%4];"
                 : "=r"(r[0]), "=r"(r[1]), "=r"(r[2]), "=r"(r[3]) : "r"(addr));
}
__device__ __forceinline__ void ldsm_x4_t(uint32_t (&r)[4], uint32_t addr) {
    asm volatile("ldmatrix.sync.aligned.m8n8.x4.trans.shared.b16 {%0,%1,%2,%3}, [%4];"
                 : "=r"(r[0]), "=r"(r[1]), "=r"(r[2]), "=r"(r[3]) : "r"(addr));
}
__device__ __forceinline__ void mma16816(float (&d)[4], const uint32_t (&a)[4],
                                         uint32_t b0, uint32_t b1) {
    asm volatile("mma.sync.aligned.m16n8k16.row.col.f32.f16.f16.f32 "
                 "{%0,%1,%2,%3}, {%4,%5,%6,%7}, {%8,%9}, {%0,%1,%2,%3};"
                 : "+f"(d[0]), "+f"(d[1]), "+f"(d[2]), "+f"(d[3])
                 : "r"(a[0]), "r"(a[1]), "r"(a[2]), "r"(a[3]), "r"(b0), "r"(b1));
}
__device__ __forceinline__ void cp16(uint32_t dst, const void* src, int sz) {
    asm volatile("cp.async.cg.shared.global [%0], [%1], 16, %2;"
                 :: "r"(dst), "l"(src), "r"(sz));
}
__device__ __forceinline__ void cp_commit() { asm volatile("cp.async.commit_group;"); }
template <int K>
__device__ __forceinline__ void cp_wait() { asm volatile("cp.async.wait_group %0;" :: "n"(K)); }

// ---------------------------------------------------------------------------
// Index width detection
// ---------------------------------------------------------------------------
__global__ void detect_idx_kernel(const void* __restrict__ srcv) {
    const unsigned long long* p = (const unsigned long long*)srcv;
    int ok = 1;
    #pragma unroll
    for (int i = 0; i < 8; i++)
        if (p[i] >= (unsigned long long)N_NODES) ok = 0;
    g_idx64 = ok;
}

// ---------------------------------------------------------------------------
// Pack Xs = [hi(x) | lo(x)] where x = [h | softmax(cls)]
// ---------------------------------------------------------------------------
__global__ void prep_x_kernel(const float* __restrict__ h,
                              const float* __restrict__ cls) {
    int idx = blockIdx.x * blockDim.x + threadIdx.x;
    if (idx >= N_NODES * XDIM) return;
    int n = idx >> 7;
    int j = idx & 127;
    float v;
    if (j < H_DIMC) {
        v = h[(size_t)n * H_DIMC + j];
    } else {
        int c = j - H_DIMC;
        float4 l = *(const float4*)(cls + (size_t)n * 4);
        float m = fmaxf(fmaxf(l.x, l.y), fmaxf(l.z, l.w));
        float e0 = expf(l.x - m), e1 = expf(l.y - m);
        float e2 = expf(l.z - m), e3 = expf(l.w - m);
        float inv = 1.0f / (e0 + e1 + e2 + e3);
        float ec = (c == 0) ? e0 : (c == 1) ? e1 : (c == 2) ? e2 : e3;
        v = ec * inv;
    }
    __half hi = __float2half_rn(v);
    __half lo = __float2half_rn(v - __half2float(hi));
    size_t base = (size_t)n * KSP;
    g_Xs[base + j]       = hi;
    g_Xs[base + 128 + j] = lo;
}

// ---------------------------------------------------------------------------
// Pack Ws: rows k and 128+k both = hi(Wg[k])
// ---------------------------------------------------------------------------
__global__ void prep_w_kernel(const float* __restrict__ W1) {
    int idx = blockIdx.x * blockDim.x + threadIdx.x;
    if (idx >= XDIM * CTOT) return;
    int k = idx >> 9;
    int c = idx & 511;
    float w = (c < HIDDEN) ? W1[(size_t)k * HIDDEN + c]
                           : W1[(size_t)(130 + k) * HIDDEN + (c - HIDDEN)];
    __half hi = __float2half_rn(w);
    g_Ws[(size_t)k * CTOT + c]         = hi;
    g_Ws[(size_t)(128 + k) * CTOT + c] = hi;
}

// ---------------------------------------------------------------------------
// Tensor-core node GEMM (UNCHANGED: 91.6us, protected)
// ---------------------------------------------------------------------------
#define BM 128
#define BN 128
#define BKC 64
#define NCHUNK (KSP / BKC)               // 4
#define WS_ROW 136
#define AS_ROW 72
#define WS_BYTES (KSP * WS_ROW * 2)       // 69632
#define AS_BUF_BYTES (BM * AS_ROW * 2)    // 18432
#define GEMM_SMEM (WS_BYTES + 2 * AS_BUF_BYTES)  // 106496
#define NMT ((N_NODES + BM - 1) / BM)     // 782
#define GRID_Y 74

__device__ __forceinline__ void load_a_chunk(uint32_t s_as, int mt, int c, int tid) {
    #pragma unroll
    for (int i = 0; i < 4; i++) {
        int idx = tid + i * 256;         // 0..1023
        int r = idx >> 3;                // 0..127
        int q = idx & 7;                 // 8 x 16B per 64-half row
        int m = mt * BM + r;
        const __half* src = g_Xs + (size_t)(m < N_NODES ? m : 0) * KSP + c * BKC + q * 8;
        cp16(s_as + (r * AS_ROW + q * 8) * 2, src, (m < N_NODES) ? 16 : 0);
    }
}

__global__ void __launch_bounds__(256, 2) node_mma_kernel(const float* __restrict__ b1) {
    extern __shared__ char smem[];
    const uint32_t s_ws = smem_u32(smem);
    const uint32_t s_as = s_ws + WS_BYTES;

    const int tid  = threadIdx.x;
    const int lane = tid & 31;
    const int wid  = tid >> 5;
    const int wm   = wid & 1;
    const int wn   = wid >> 1;
    const int n0   = blockIdx.x * BN;
    const int lane15 = lane & 15;
    const int ksel   = (lane >> 4) << 3;

    #pragma unroll
    for (int i = 0; i < 16; i++) {
        int idx = tid + i * 256;
        int r = idx >> 4;
        int q = idx & 15;
        cp16(s_ws + (r * WS_ROW + q * 8) * 2,
             g_Ws + (size_t)r * CTOT + n0 + q * 8, 16);
    }
    load_a_chunk(s_as, blockIdx.y, 0, tid);
    cp_commit();

    const bool bias = (n0 < HIDDEN);
    int gc = 0;

    for (int mt = blockIdx.y; mt < NMT; mt += GRID_Y) {
        float acc[4][4][4];
        #pragma unroll
        for (int mi = 0; mi < 4; mi++)
            #pragma unroll
            for (int ni = 0; ni < 4; ni++)
                #pragma unroll
                for (int t = 0; t < 4; t++) acc[mi][ni][t] = 0.0f;

        for (int c = 0; c < NCHUNK; c++, gc++) {
            cp_wait<0>();
            __syncthreads();
            if (c + 1 < NCHUNK) {
                load_a_chunk(s_as + ((gc + 1) & 1) * AS_BUF_BYTES, mt, c + 1, tid);
                cp_commit();
            } else if (mt + GRID_Y < NMT) {
                load_a_chunk(s_as + ((gc + 1) & 1) * AS_BUF_BYTES, mt + GRID_Y, 0, tid);
                cp_commit();
            }
            const uint32_t abuf = s_as + (gc & 1) * AS_BUF_BYTES;
            #pragma unroll
            for (int ks = 0; ks < 4; ks++) {
                uint32_t Af[4][4], Bf[2][4];
                #pragma unroll
                for (int mi = 0; mi < 4; mi++) {
                    uint32_t addr = abuf +
                        ((wm * 64 + mi * 16 + lane15) * AS_ROW + ks * 16 + ksel) * 2;
                    ldsm_x4(Af[mi], addr);
                }
                #pragma unroll
                for (int np = 0; np < 2; np++) {
                    uint32_t addr = s_ws +
                        ((c * BKC + ks * 16 + lane15) * WS_ROW + wn * 32 + np * 16 + ksel) * 2;
                    ldsm_x4_t(Bf[np], addr);
                }
                #pragma unroll
                for (int mi = 0; mi < 4; mi++)
                    #pragma unroll
                    for (int np = 0; np < 2; np++) {
                        mma16816(acc[mi][np * 2 + 0], Af[mi], Bf[np][0], Bf[np][1]);
                        mma16816(acc[mi][np * 2 + 1], Af[mi], Bf[np][2], Bf[np][3]);
                    }
            }
        }

        const int m_base = mt * BM + wm * 64;
        #pragma unroll
        for (int ni = 0; ni < 4; ni++) {
            int col = n0 + wn * 32 + ni * 8 + ((lane & 3) << 1);
            float bb0 = 0.f, bb1 = 0.f;
            if (bias) { bb0 = b1[col]; bb1 = b1[col + 1]; }
            #pragma unroll
            for (int mi = 0; mi < 4; mi++) {
                int r0 = m_base + mi * 16 + (lane >> 2);
                float* a = acc[mi][ni];
                if (r0 < N_NODES)
                    *(__half2*)(g_Ch + (size_t)r0 * CTOT + col) =
                        __floats2half2_rn(a[0] + bb0, a[1] + bb1);
                int r1 = r0 + 8;
                if (r1 < N_NODES)
                    *(__half2*)(g_Ch + (size_t)r1 * CTOT + col) =
                        __floats2half2_rn(a[2] + bb0, a[3] + bb1);
            }
        }
    }
}

// ---------------------------------------------------------------------------
// Edge kernel: PER-WARP cp.async pipeline (round-10 structure, fill FIXED:
// each lane copies its FULL 128-byte quarter = 8 x 16B chunks; previously
// only 4 chunks were issued, leaving half of every staged row unwritten).
// ---------------------------------------------------------------------------
#define EDGE_SMEM (8 * 2 * 4096)   // 65536: 8 warps x 2 stages x 4KB

__global__ void __launch_bounds__(256, 2) edge_kernel(
    const float* __restrict__ polar,
    const void*  __restrict__ srcv,
    const void*  __restrict__ dstv,
    const float* __restrict__ W1,
    const float* __restrict__ gamma,
    const float* __restrict__ beta,
    const float* __restrict__ W2,
    const float* __restrict__ b2,
    float* __restrict__ out)
{
    extern __shared__ char esmem[];

    const int lane = threadIdx.x & 31;
    const int wid  = (threadIdx.x >> 5);
    const int warp = (blockIdx.x * blockDim.x + threadIdx.x) >> 5;
    const int nwarps = (gridDim.x * blockDim.x) >> 5;
    const int j0 = lane * 8;

    char* wbuf = esmem + wid * 8192;                 // this warp's 2 stages
    const uint32_t wbuf_u = smem_u32(wbuf);

    float wp0[8], wp1[8], ga[8], be[8], w2a[8], w2b[8];
    #pragma unroll
    for (int i = 0; i < 8; i++) {
        int j = j0 + i;
        wp0[i] = W1[(size_t)128 * HIDDEN + j];
        wp1[i] = W1[(size_t)129 * HIDDEN + j];
        ga[i]  = gamma[j];
        be[i]  = beta[j];
        w2a[i] = W2[j * 2 + 0];
        w2b[i] = W2[j * 2 + 1];
    }
    const float bias0 = b2[0], bias1 = b2[1];

    const bool is64 = (g_idx64 != 0);
    const long long* src64 = (const long long*)srcv;
    const long long* dst64 = (const long long*)dstv;
    const int*       src32 = (const int*)srcv;
    const int*       dst32 = (const int*)dstv;

    // fill-lane assignment (constant per thread)
    const int f_el  = lane >> 3;          // edge within group 0..3
    const int f_sub = lane & 7;           // 0..3 = A row quarters, 4..7 = B row quarters
    const bool f_B  = (f_sub >= 4);
    const int f_off = (f_sub & 3) * 64;   // halves offset within the 256-half row (128B quarter)
    const uint32_t f_dst_off = (uint32_t)(f_el * 1024 + (f_B ? 512 : 0) + (f_sub & 3) * 128);

    const int step = 4 * nwarps;
    const int e0 = warp * 4;

    // fill one stage (4 edges) into buffer `par` for edge-group base `eb`
    auto fill = [&](int par, int eb) {
        if (eb < E_EDGES) {
            int e = eb + f_el;
            int node = f_B ? (is64 ? (int)dst64[e] : dst32[e])
                           : (is64 ? (int)src64[e] : src32[e]);
            const __half* row = g_Ch + (size_t)node * CTOT + (f_B ? HIDDEN : 0) + f_off;
            uint32_t dst = wbuf_u + (uint32_t)par * 4096 + f_dst_off;
            #pragma unroll
            for (int j = 0; j < 8; j++)             // FIXED: full 128B (8 x 16B)
                cp16(dst + j * 16, row + j * 8, 16);
        }
        cp_commit();   // commit unconditionally to keep group counts aligned
    };

    if (e0 >= E_EDGES) return;

    fill(0, e0);
    fill(1, e0 + step);

    int par = 0;
    for (int e = e0; e < E_EDGES; e += step) {
        cp_wait<1>();        // this lane's stage `par` copies complete
        __syncwarp();        // warp barrier: all lanes' copies complete + visible

        const char* sb = wbuf + par * 4096;
        float4 p01 = *(const float4*)(polar + (size_t)e * 2);
        float4 p23 = *(const float4*)(polar + (size_t)e * 2 + 4);
        float px[4] = {p01.x, p01.z, p23.x, p23.z};
        float py[4] = {p01.y, p01.w, p23.y, p23.w};

        float o[8];
        #pragma unroll
        for (int ei = 0; ei < 4; ei++) {
            const char* ebuf = sb + ei * 1024;
            uint4 va = *(const uint4*)(ebuf + lane * 16);
            uint4 vb = *(const uint4*)(ebuf + 512 + lane * 16);

            float2 a01 = __half22float2(*reinterpret_cast<const __half2*>(&va.x));
            float2 a23 = __half22float2(*reinterpret_cast<const __half2*>(&va.y));
            float2 a45 = __half22float2(*reinterpret_cast<const __half2*>(&va.z));
            float2 a67 = __half22float2(*reinterpret_cast<const __half2*>(&va.w));
            float2 b01 = __half22float2(*reinterpret_cast<const __half2*>(&vb.x));
            float2 b23 = __half22float2(*reinterpret_cast<const __half2*>(&vb.y));
            float2 b45 = __half22float2(*reinterpret_cast<const __half2*>(&vb.z));
            float2 b67 = __half22float2(*reinterpret_cast<const __half2*>(&vb.w));

            float z[8];
            z[0] = a01.x + b01.x; z[1] = a01.y + b01.y;
            z[2] = a23.x + b23.x; z[3] = a23.y + b23.y;
            z[4] = a45.x + b45.x; z[5] = a45.y + b45.y;
            z[6] = a67.x + b67.x; z[7] = a67.y + b67.y;
            #pragma unroll
            for (int i = 0; i < 8; i++)
                z[i] = fmaf(px[ei], wp0[i], fmaf(py[ei], wp1[i], z[i]));

            float s1v = 0.f, s2v = 0.f;
            #pragma unroll
            for (int i = 0; i < 8; i++) {
                s1v += z[i];
                s2v = fmaf(z[i], z[i], s2v);
            }
            #pragma unroll
            for (int o2 = 16; o2 > 0; o2 >>= 1) {
                s1v += __shfl_xor_sync(0xFFFFFFFFu, s1v, o2);
                s2v += __shfl_xor_sync(0xFFFFFFFFu, s2v, o2);
            }
            const float mean = s1v * (1.0f / 256.0f);
            const float var  = fmaf(-mean, mean, s2v * (1.0f / 256.0f));
            const float rstd = rsqrtf(var + 1e-5f);

            float acc0 = 0.f, acc1 = 0.f;
            #pragma unroll
            for (int i = 0; i < 8; i++) {
                float y = fmaf((z[i] - mean) * rstd, ga[i], be[i]);
                y = fmaxf(y, 0.0f);
                acc0 = fmaf(y, w2a[i], acc0);
                acc1 = fmaf(y, w2b[i], acc1);
            }
            #pragma unroll
            for (int o2 = 16; o2 > 0; o2 >>= 1) {
                acc0 += __shfl_xor_sync(0xFFFFFFFFu, acc0, o2);
                acc1 += __shfl_xor_sync(0xFFFFFFFFu, acc1, o2);
            }
            o[ei * 2 + 0] = acc0 + bias0;
            o[ei * 2 + 1] = acc1 + bias1;
        }
        if (lane == 0) {
            *(float4*)(out + (size_t)e * 2)     = make_float4(o[0], o[1], o[2], o[3]);
            *(float4*)(out + (size_t)e * 2 + 4) = make_float4(o[4], o[5], o[6], o[7]);
        }

        __syncwarp();                    // all lanes done reading stage `par`
        fill(par, e + 2 * step);         // refill the just-consumed stage
        par ^= 1;
    }
}

// ---------------------------------------------------------------------------
// Launch
// ---------------------------------------------------------------------------
extern "C" void kernel_launch(void* const* d_in, const int* in_sizes, int n_in,
                              void* d_out, int out_size) {
    const float* h     = (const float*)d_in[0];
    const float* cls   = (const float*)d_in[1];
    const float* polar = (const float*)d_in[2];
    const void*  src   = d_in[3];
    const void*  dst   = d_in[4];
    const float* W1    = (const float*)d_in[5];
    const float* b1    = (const float*)d_in[6];
    const float* gamma = (const float*)d_in[7];
    const float* beta  = (const float*)d_in[8];
    const float* W2    = (const float*)d_in[9];
    const float* b2    = (const float*)d_in[10];
    float* out = (float*)d_out;

    (void)in_sizes; (void)n_in; (void)out_size;

    cudaFuncSetAttribute(node_mma_kernel,
                         cudaFuncAttributeMaxDynamicSharedMemorySize, GEMM_SMEM);
    cudaFuncSetAttribute(edge_kernel,
                         cudaFuncAttributeMaxDynamicSharedMemorySize, EDGE_SMEM);

    detect_idx_kernel<<<1, 1>>>(src);

    {
        int total = N_NODES * XDIM;
        prep_x_kernel<<<(total + 255) / 256, 256>>>(h, cls);
    }
    {
        int total = XDIM * CTOT;
        prep_w_kernel<<<(total + 255) / 256, 256>>>(W1);
    }
    {
        dim3 grid(CTOT / BN, GRID_Y);   // (4, 74) = 296 CTAs -> 2 CTAs/SM
        node_mma_kernel<<<grid, 256, GEMM_SMEM>>>(b1);
    }
    {
        edge_kernel<<<1184, 256, EDGE_SMEM>>>(polar, src, dst, W1, gamma, beta, W2, b2, out);
    }
}

// round 12
// speedup vs baseline: 1.4988x; 1.4988x over previous
#include <cuda_runtime.h>
#include <cuda_fp16.h>
#include <cstdint>

// Problem constants
#define N_NODES 100000
#define E_EDGES 1000000
#define H_DIMC  124
#define XDIM    128
#define HIDDEN  256
#define CTOT    512     // A (256) || B (256)
#define KSP     256     // split-K: [hi | lo]

// ---------------------------------------------------------------------------
// Static device scratch
// ---------------------------------------------------------------------------
__device__ __half g_Xs[(size_t)N_NODES * KSP];   // [N,256] fp16 split X (51MB)
__device__ __half g_Ws[(size_t)KSP * CTOT];      // [256,512] fp16: rows k and 128+k = hi(Wg[k])
__device__ __half g_Ch[(size_t)N_NODES * CTOT];  // [N,512] fp16 = [A|B], b1 folded into A
__device__ int    g_idx64;

// ---------------------------------------------------------------------------
// PTX helpers
// ---------------------------------------------------------------------------
__device__ __forceinline__ uint32_t smem_u32(const void* p) {
    return (uint32_t)__cvta_generic_to_shared(p);
}
__device__ __forceinline__ void ldsm_x4(uint32_t (&r)[4], uint32_t addr) {
    asm volatile("ldmatrix.sync.aligned.m8n8.x4.shared.b16 {%0,%1,%2,%3}, [%4];"
                 : "=r"(r[0]), "=r"(r[1]), "=r"(r[2]), "=r"(r[3]) : "r"(addr));
}
__device__ __forceinline__ void ldsm_x4_t(uint32_t (&r)[4], uint32_t addr) {
    asm volatile("ldmatrix.sync.aligned.m8n8.x4.trans.shared.b16 {%0,%1,%2,%3}, [%4];"
                 : "=r"(r[0]), "=r"(r[1]), "=r"(r[2]), "=r"(r[3]) : "r"(addr));
}
__device__ __forceinline__ void mma16816(float (&d)[4], const uint32_t (&a)[4],
                                         uint32_t b0, uint32_t b1) {
    asm volatile("mma.sync.aligned.m16n8k16.row.col.f32.f16.f16.f32 "
                 "{%0,%1,%2,%3}, {%4,%5,%6,%7}, {%8,%9}, {%0,%1,%2,%3};"
                 : "+f"(d[0]), "+f"(d[1]), "+f"(d[2]), "+f"(d[3])
                 : "r"(a[0]), "r"(a[1]), "r"(a[2]), "r"(a[3]), "r"(b0), "r"(b1));
}
__device__ __forceinline__ void cp16(uint32_t dst, const void* src, int sz) {
    asm volatile("cp.async.cg.shared.global [%0], [%1], 16, %2;"
                 :: "r"(dst), "l"(src), "r"(sz));
}
__device__ __forceinline__ void cp_commit() { asm volatile("cp.async.commit_group;"); }
template <int K>
__device__ __forceinline__ void cp_wait() { asm volatile("cp.async.wait_group %0;" :: "n"(K)); }

// ---------------------------------------------------------------------------
// Index width detection
// ---------------------------------------------------------------------------
__global__ void detect_idx_kernel(const void* __restrict__ srcv) {
    const unsigned long long* p = (const unsigned long long*)srcv;
    int ok = 1;
    #pragma unroll
    for (int i = 0; i < 8; i++)
        if (p[i] >= (unsigned long long)N_NODES) ok = 0;
    g_idx64 = ok;
}

// ---------------------------------------------------------------------------
// Pack Xs = [hi(x) | lo(x)] where x = [h | softmax(cls)]
// ---------------------------------------------------------------------------
__global__ void prep_x_kernel(const float* __restrict__ h,
                              const float* __restrict__ cls) {
    int idx = blockIdx.x * blockDim.x + threadIdx.x;
    if (idx >= N_NODES * XDIM) return;
    int n = idx >> 7;
    int j = idx & 127;
    float v;
    if (j < H_DIMC) {
        v = h[(size_t)n * H_DIMC + j];
    } else {
        int c = j - H_DIMC;
        float4 l = *(const float4*)(cls + (size_t)n * 4);
        float m = fmaxf(fmaxf(l.x, l.y), fmaxf(l.z, l.w));
        float e0 = expf(l.x - m), e1 = expf(l.y - m);
        float e2 = expf(l.z - m), e3 = expf(l.w - m);
        float inv = 1.0f / (e0 + e1 + e2 + e3);
        float ec = (c == 0) ? e0 : (c == 1) ? e1 : (c == 2) ? e2 : e3;
        v = ec * inv;
    }
    __half hi = __float2half_rn(v);
    __half lo = __float2half_rn(v - __half2float(hi));
    size_t base = (size_t)n * KSP;
    g_Xs[base + j]       = hi;
    g_Xs[base + 128 + j] = lo;
}

// ---------------------------------------------------------------------------
// Pack Ws: rows k and 128+k both = hi(Wg[k])
// ---------------------------------------------------------------------------
__global__ void prep_w_kernel(const float* __restrict__ W1) {
    int idx = blockIdx.x * blockDim.x + threadIdx.x;
    if (idx >= XDIM * CTOT) return;
    int k = idx >> 9;
    int c = idx & 511;
    float w = (c < HIDDEN) ? W1[(size_t)k * HIDDEN + c]
                           : W1[(size_t)(130 + k) * HIDDEN + (c - HIDDEN)];
    __half hi = __float2half_rn(w);
    g_Ws[(size_t)k * CTOT + c]         = hi;
    g_Ws[(size_t)(128 + k) * CTOT + c] = hi;
}

// ---------------------------------------------------------------------------
// Tensor-core node GEMM (UNCHANGED: 91.6us, protected)
// ---------------------------------------------------------------------------
#define BM 128
#define BN 128
#define BKC 64
#define NCHUNK (KSP / BKC)               // 4
#define WS_ROW 136
#define AS_ROW 72
#define WS_BYTES (KSP * WS_ROW * 2)       // 69632
#define AS_BUF_BYTES (BM * AS_ROW * 2)    // 18432
#define GEMM_SMEM (WS_BYTES + 2 * AS_BUF_BYTES)  // 106496
#define NMT ((N_NODES + BM - 1) / BM)     // 782
#define GRID_Y 74

__device__ __forceinline__ void load_a_chunk(uint32_t s_as, int mt, int c, int tid) {
    #pragma unroll
    for (int i = 0; i < 4; i++) {
        int idx = tid + i * 256;         // 0..1023
        int r = idx >> 3;                // 0..127
        int q = idx & 7;                 // 8 x 16B per 64-half row
        int m = mt * BM + r;
        const __half* src = g_Xs + (size_t)(m < N_NODES ? m : 0) * KSP + c * BKC + q * 8;
        cp16(s_as + (r * AS_ROW + q * 8) * 2, src, (m < N_NODES) ? 16 : 0);
    }
}

__global__ void __launch_bounds__(256, 2) node_mma_kernel(const float* __restrict__ b1) {
    extern __shared__ char smem[];
    const uint32_t s_ws = smem_u32(smem);
    const uint32_t s_as = s_ws + WS_BYTES;

    const int tid  = threadIdx.x;
    const int lane = tid & 31;
    const int wid  = tid >> 5;
    const int wm   = wid & 1;
    const int wn   = wid >> 1;
    const int n0   = blockIdx.x * BN;
    const int lane15 = lane & 15;
    const int ksel   = (lane >> 4) << 3;

    #pragma unroll
    for (int i = 0; i < 16; i++) {
        int idx = tid + i * 256;
        int r = idx >> 4;
        int q = idx & 15;
        cp16(s_ws + (r * WS_ROW + q * 8) * 2,
             g_Ws + (size_t)r * CTOT + n0 + q * 8, 16);
    }
    load_a_chunk(s_as, blockIdx.y, 0, tid);
    cp_commit();

    const bool bias = (n0 < HIDDEN);
    int gc = 0;

    for (int mt = blockIdx.y; mt < NMT; mt += GRID_Y) {
        float acc[4][4][4];
        #pragma unroll
        for (int mi = 0; mi < 4; mi++)
            #pragma unroll
            for (int ni = 0; ni < 4; ni++)
                #pragma unroll
                for (int t = 0; t < 4; t++) acc[mi][ni][t] = 0.0f;

        for (int c = 0; c < NCHUNK; c++, gc++) {
            cp_wait<0>();
            __syncthreads();
            if (c + 1 < NCHUNK) {
                load_a_chunk(s_as + ((gc + 1) & 1) * AS_BUF_BYTES, mt, c + 1, tid);
                cp_commit();
            } else if (mt + GRID_Y < NMT) {
                load_a_chunk(s_as + ((gc + 1) & 1) * AS_BUF_BYTES, mt + GRID_Y, 0, tid);
                cp_commit();
            }
            const uint32_t abuf = s_as + (gc & 1) * AS_BUF_BYTES;
            #pragma unroll
            for (int ks = 0; ks < 4; ks++) {
                uint32_t Af[4][4], Bf[2][4];
                #pragma unroll
                for (int mi = 0; mi < 4; mi++) {
                    uint32_t addr = abuf +
                        ((wm * 64 + mi * 16 + lane15) * AS_ROW + ks * 16 + ksel) * 2;
                    ldsm_x4(Af[mi], addr);
                }
                #pragma unroll
                for (int np = 0; np < 2; np++) {
                    uint32_t addr = s_ws +
                        ((c * BKC + ks * 16 + lane15) * WS_ROW + wn * 32 + np * 16 + ksel) * 2;
                    ldsm_x4_t(Bf[np], addr);
                }
                #pragma unroll
                for (int mi = 0; mi < 4; mi++)
                    #pragma unroll
                    for (int np = 0; np < 2; np++) {
                        mma16816(acc[mi][np * 2 + 0], Af[mi], Bf[np][0], Bf[np][1]);
                        mma16816(acc[mi][np * 2 + 1], Af[mi], Bf[np][2], Bf[np][3]);
                    }
            }
        }

        const int m_base = mt * BM + wm * 64;
        #pragma unroll
        for (int ni = 0; ni < 4; ni++) {
            int col = n0 + wn * 32 + ni * 8 + ((lane & 3) << 1);
            float bb0 = 0.f, bb1 = 0.f;
            if (bias) { bb0 = b1[col]; bb1 = b1[col + 1]; }
            #pragma unroll
            for (int mi = 0; mi < 4; mi++) {
                int r0 = m_base + mi * 16 + (lane >> 2);
                float* a = acc[mi][ni];
                if (r0 < N_NODES)
                    *(__half2*)(g_Ch + (size_t)r0 * CTOT + col) =
                        __floats2half2_rn(a[0] + bb0, a[1] + bb1);
                int r1 = r0 + 8;
                if (r1 < N_NODES)
                    *(__half2*)(g_Ch + (size_t)r1 * CTOT + col) =
                        __floats2half2_rn(a[2] + bb0, a[3] + bb1);
            }
        }
    }
}

// ---------------------------------------------------------------------------
// Edge kernel: round-7 register-gather structure (proven ~250us), with
// instruction-count reductions:
//  - z = A+B via __hadd2 (fp16 add) before widening   (-12 instr/edge)
//  - paired half-warp reductions for (s1,s2) and (acc0,acc1): one offset-16
//    butterfly splits the pair into lane halves, then a single 4-level tree
//    reduces both simultaneously                       (-10 instr/edge)
// ---------------------------------------------------------------------------
__global__ void __launch_bounds__(256, 2) edge_kernel(
    const float* __restrict__ polar,
    const void*  __restrict__ srcv,
    const void*  __restrict__ dstv,
    const float* __restrict__ W1,
    const float* __restrict__ gamma,
    const float* __restrict__ beta,
    const float* __restrict__ W2,
    const float* __restrict__ b2,
    float* __restrict__ out)
{
    const int lane = threadIdx.x & 31;
    const int warp = (blockIdx.x * blockDim.x + threadIdx.x) >> 5;
    const int nwarps = (gridDim.x * blockDim.x) >> 5;
    const int j0 = lane * 8;
    const unsigned FULL = 0xFFFFFFFFu;

    float wp0[8], wp1[8], ga[8], be[8], w2a[8], w2b[8];
    #pragma unroll
    for (int i = 0; i < 8; i++) {
        int j = j0 + i;
        wp0[i] = W1[(size_t)128 * HIDDEN + j];
        wp1[i] = W1[(size_t)129 * HIDDEN + j];
        ga[i]  = gamma[j];
        be[i]  = beta[j];
        w2a[i] = W2[j * 2 + 0];
        w2b[i] = W2[j * 2 + 1];
    }
    const float bias0 = b2[0], bias1 = b2[1];
    const float mybias = (lane < 16) ? bias0 : bias1;

    const bool is64 = (g_idx64 != 0);
    const long long* src64 = (const long long*)srcv;
    const long long* dst64 = (const long long*)dstv;
    const int*       src32 = (const int*)srcv;
    const int*       dst32 = (const int*)dstv;

    for (int e = warp * 4; e < E_EDGES; e += 4 * nwarps) {
        int s[4], d[4];
        if (is64) {
            longlong2 S0 = *(const longlong2*)(src64 + e);
            longlong2 S1 = *(const longlong2*)(src64 + e + 2);
            longlong2 D0 = *(const longlong2*)(dst64 + e);
            longlong2 D1 = *(const longlong2*)(dst64 + e + 2);
            s[0] = (int)S0.x; s[1] = (int)S0.y; s[2] = (int)S1.x; s[3] = (int)S1.y;
            d[0] = (int)D0.x; d[1] = (int)D0.y; d[2] = (int)D1.x; d[3] = (int)D1.y;
        } else {
            int4 S = *(const int4*)(src32 + e);
            int4 D = *(const int4*)(dst32 + e);
            s[0] = S.x; s[1] = S.y; s[2] = S.z; s[3] = S.w;
            d[0] = D.x; d[1] = D.y; d[2] = D.z; d[3] = D.w;
        }
        float4 p01 = *(const float4*)(polar + (size_t)e * 2);
        float4 p23 = *(const float4*)(polar + (size_t)e * 2 + 4);
        float px[4] = {p01.x, p01.z, p23.x, p23.z};
        float py[4] = {p01.y, p01.w, p23.y, p23.w};

        uint4 va[4], vb[4];
        #pragma unroll
        for (int ei = 0; ei < 4; ei++) {
            va[ei] = *(const uint4*)(g_Ch + (size_t)s[ei] * CTOT + j0);
            vb[ei] = *(const uint4*)(g_Ch + (size_t)d[ei] * CTOT + HIDDEN + j0);
        }

        float vout[4];
        #pragma unroll
        for (int ei = 0; ei < 4; ei++) {
            // z = A + B in fp16x2, then widen (one extra fp16 rounding, ok)
            const __half2* ah = reinterpret_cast<const __half2*>(&va[ei]);
            const __half2* bh = reinterpret_cast<const __half2*>(&vb[ei]);
            float2 zp0 = __half22float2(__hadd2(ah[0], bh[0]));
            float2 zp1 = __half22float2(__hadd2(ah[1], bh[1]));
            float2 zp2 = __half22float2(__hadd2(ah[2], bh[2]));
            float2 zp3 = __half22float2(__hadd2(ah[3], bh[3]));
            float z[8] = {zp0.x, zp0.y, zp1.x, zp1.y, zp2.x, zp2.y, zp3.x, zp3.y};
            #pragma unroll
            for (int i = 0; i < 8; i++)
                z[i] = fmaf(px[ei], wp0[i], fmaf(py[ei], wp1[i], z[i]));

            float s1v = 0.f, s2v = 0.f;
            #pragma unroll
            for (int i = 0; i < 8; i++) {
                s1v += z[i];
                s2v = fmaf(z[i], z[i], s2v);
            }
            // paired reduction: split (s1,s2) across lane halves
            s1v += __shfl_xor_sync(FULL, s1v, 16);
            s2v += __shfl_xor_sync(FULL, s2v, 16);
            float ms = (lane < 16) ? s1v : s2v;
            #pragma unroll
            for (int o2 = 8; o2 > 0; o2 >>= 1)
                ms += __shfl_xor_sync(FULL, ms, o2);
            // lanes 0-15 hold sum(s1), lanes 16-31 hold sum(s2); broadcast both
            const float s1t = __shfl_sync(FULL, ms, lane & 15);
            const float s2t = __shfl_sync(FULL, ms, (lane & 15) | 16);

            const float mean = s1t * (1.0f / 256.0f);
            const float var  = fmaf(-mean, mean, s2t * (1.0f / 256.0f));
            const float rstd = rsqrtf(var + 1e-5f);

            float acc0 = 0.f, acc1 = 0.f;
            #pragma unroll
            for (int i = 0; i < 8; i++) {
                float y = fmaf((z[i] - mean) * rstd, ga[i], be[i]);
                y = fmaxf(y, 0.0f);
                acc0 = fmaf(y, w2a[i], acc0);
                acc1 = fmaf(y, w2b[i], acc1);
            }
            // paired reduction for (acc0, acc1)
            acc0 += __shfl_xor_sync(FULL, acc0, 16);
            acc1 += __shfl_xor_sync(FULL, acc1, 16);
            float av = (lane < 16) ? acc0 : acc1;
            #pragma unroll
            for (int o2 = 8; o2 > 0; o2 >>= 1)
                av += __shfl_xor_sync(FULL, av, o2);
            vout[ei] = av + mybias;   // lanes 0-15: out0, lanes 16-31: out1
        }

        // gather results to lane 0 and write two float4
        float o[8];
        #pragma unroll
        for (int ei = 0; ei < 4; ei++) {
            o[ei * 2 + 0] = __shfl_sync(FULL, vout[ei], 0);
            o[ei * 2 + 1] = __shfl_sync(FULL, vout[ei], 16);
        }
        if (lane == 0) {
            *(float4*)(out + (size_t)e * 2)     = make_float4(o[0], o[1], o[2], o[3]);
            *(float4*)(out + (size_t)e * 2 + 4) = make_float4(o[4], o[5], o[6], o[7]);
        }
    }
}

// ---------------------------------------------------------------------------
// Launch
// ---------------------------------------------------------------------------
extern "C" void kernel_launch(void* const* d_in, const int* in_sizes, int n_in,
                              void* d_out, int out_size) {
    const float* h     = (const float*)d_in[0];
    const float* cls   = (const float*)d_in[1];
    const float* polar = (const float*)d_in[2];
    const void*  src   = d_in[3];
    const void*  dst   = d_in[4];
    const float* W1    = (const float*)d_in[5];
    const float* b1    = (const float*)d_in[6];
    const float* gamma = (const float*)d_in[7];
    const float* beta  = (const float*)d_in[8];
    const float* W2    = (const float*)d_in[9];
    const float* b2    = (const float*)d_in[10];
    float* out = (float*)d_out;

    (void)in_sizes; (void)n_in; (void)out_size;

    cudaFuncSetAttribute(node_mma_kernel,
                         cudaFuncAttributeMaxDynamicSharedMemorySize, GEMM_SMEM);

    detect_idx_kernel<<<1, 1>>>(src);

    {
        int total = N_NODES * XDIM;
        prep_x_kernel<<<(total + 255) / 256, 256>>>(h, cls);
    }
    {
        int total = XDIM * CTOT;
        prep_w_kernel<<<(total + 255) / 256, 256>>>(W1);
    }
    {
        dim3 grid(CTOT / BN, GRID_Y);   // (4, 74) = 296 CTAs -> 2 CTAs/SM
        node_mma_kernel<<<grid, 256, GEMM_SMEM>>>(b1);
    }
    {
        edge_kernel<<<1184, 256>>>(polar, src, dst, W1, gamma, beta, W2, b2, out);
    }
}

// round 13
// speedup vs baseline: 1.5350x; 1.0242x over previous
#include <cuda_runtime.h>
#include <cuda_fp16.h>
#include <cstdint>

// Problem constants
#define N_NODES 100000
#define E_EDGES 1000000
#define H_DIMC  124
#define XDIM    128
#define HIDDEN  256
#define CTOT    512     // A (256) || B (256)
#define KSP     256     // split-K: [hi | lo]

// ---------------------------------------------------------------------------
// Static device scratch
// ---------------------------------------------------------------------------
__device__ __half g_Xs[(size_t)N_NODES * KSP];   // [N,256] fp16 split X (51MB)
__device__ __half g_Ws[(size_t)XDIM * CTOT];     // [128,512] fp16 = hi(Wg)
__device__ __half g_Ch[(size_t)N_NODES * CTOT];  // [N,512] fp16 = [A|B], b1 folded into A
__device__ int    g_idx64;

// ---------------------------------------------------------------------------
// PTX helpers
// ---------------------------------------------------------------------------
__device__ __forceinline__ uint32_t smem_u32(const void* p) {
    return (uint32_t)__cvta_generic_to_shared(p);
}
__device__ __forceinline__ void ldsm_x4(uint32_t (&r)[4], uint32_t addr) {
    asm volatile("ldmatrix.sync.aligned.m8n8.x4.shared.b16 {%0,%1,%2,%3}, [%4];"
                 : "=r"(r[0]), "=r"(r[1]), "=r"(r[2]), "=r"(r[3]) : "r"(addr));
}
__device__ __forceinline__ void ldsm_x4_t(uint32_t (&r)[4], uint32_t addr) {
    asm volatile("ldmatrix.sync.aligned.m8n8.x4.trans.shared.b16 {%0,%1,%2,%3}, [%4];"
                 : "=r"(r[0]), "=r"(r[1]), "=r"(r[2]), "=r"(r[3]) : "r"(addr));
}
__device__ __forceinline__ void mma16816(float (&d)[4], const uint32_t (&a)[4],
                                         uint32_t b0, uint32_t b1) {
    asm volatile("mma.sync.aligned.m16n8k16.row.col.f32.f16.f16.f32 "
                 "{%0,%1,%2,%3}, {%4,%5,%6,%7}, {%8,%9}, {%0,%1,%2,%3};"
                 : "+f"(d[0]), "+f"(d[1]), "+f"(d[2]), "+f"(d[3])
                 : "r"(a[0]), "r"(a[1]), "r"(a[2]), "r"(a[3]), "r"(b0), "r"(b1));
}
__device__ __forceinline__ void cp16(uint32_t dst, const void* src, int sz) {
    asm volatile("cp.async.cg.shared.global [%0], [%1], 16, %2;"
                 :: "r"(dst), "l"(src), "r"(sz));
}
__device__ __forceinline__ void cp_commit() { asm volatile("cp.async.commit_group;"); }
template <int K>
__device__ __forceinline__ void cp_wait() { asm volatile("cp.async.wait_group %0;" :: "n"(K)); }

// ---------------------------------------------------------------------------
// Index width detection
// ---------------------------------------------------------------------------
__global__ void detect_idx_kernel(const void* __restrict__ srcv) {
    const unsigned long long* p = (const unsigned long long*)srcv;
    int ok = 1;
    #pragma unroll
    for (int i = 0; i < 8; i++)
        if (p[i] >= (unsigned long long)N_NODES) ok = 0;
    g_idx64 = ok;
}

// ---------------------------------------------------------------------------
// Pack Xs = [hi(x) | lo(x)] where x = [h | softmax(cls)]
// ---------------------------------------------------------------------------
__global__ void prep_x_kernel(const float* __restrict__ h,
                              const float* __restrict__ cls) {
    int idx = blockIdx.x * blockDim.x + threadIdx.x;
    if (idx >= N_NODES * XDIM) return;
    int n = idx >> 7;
    int j = idx & 127;
    float v;
    if (j < H_DIMC) {
        v = h[(size_t)n * H_DIMC + j];
    } else {
        int c = j - H_DIMC;
        float4 l = *(const float4*)(cls + (size_t)n * 4);
        float m = fmaxf(fmaxf(l.x, l.y), fmaxf(l.z, l.w));
        float e0 = expf(l.x - m), e1 = expf(l.y - m);
        float e2 = expf(l.z - m), e3 = expf(l.w - m);
        float inv = 1.0f / (e0 + e1 + e2 + e3);
        float ec = (c == 0) ? e0 : (c == 1) ? e1 : (c == 2) ? e2 : e3;
        v = ec * inv;
    }
    __half hi = __float2half_rn(v);
    __half lo = __float2half_rn(v - __half2float(hi));
    size_t base = (size_t)n * KSP;
    g_Xs[base + j]       = hi;
    g_Xs[base + 128 + j] = lo;
}

// ---------------------------------------------------------------------------
// Pack Ws[k][c] = hi(Wg[k][c]) (single copy; the GEMM reuses it for the lo
// half of A via the (c&1) chunk-row wrap)
// ---------------------------------------------------------------------------
__global__ void prep_w_kernel(const float* __restrict__ W1) {
    int idx = blockIdx.x * blockDim.x + threadIdx.x;
    if (idx >= XDIM * CTOT) return;
    int k = idx >> 9;
    int c = idx & 511;
    float w = (c < HIDDEN) ? W1[(size_t)k * HIDDEN + c]
                           : W1[(size_t)(130 + k) * HIDDEN + (c - HIDDEN)];
    g_Ws[(size_t)k * CTOT + c] = __float2half_rn(w);
}

// ---------------------------------------------------------------------------
// Tensor-core node GEMM: C[N,512] = Xs[N,256] @ [Whi;Whi] (+b1 on cols<256)
// NEW tiling: BM=64, BN=128 -> 32 acc regs/thread -> 3 CTAs/SM (reg-file was
// the occupancy binder at 64 acc regs). W smem deduplicated (128 rows only;
// chunk c reads W rows (c&1)*64..). Grid (4, 111) = 444 CTAs = 148 SMs x 3.
// ---------------------------------------------------------------------------
#define BM 64
#define BN 128
#define BKC 64
#define NCHUNK (KSP / BKC)               // 4
#define WS_ROW 136                        // 272B stride, conflict-free ldsm
#define AS_ROW 72                         // 144B stride, conflict-free ldsm
#define WS_BYTES (128 * WS_ROW * 2)       // 34816 (dedup: 128 K-rows only)
#define AS_BUF_BYTES (BM * AS_ROW * 2)    // 9216
#define GEMM_SMEM (WS_BYTES + 2 * AS_BUF_BYTES)  // 53248
#define NMT ((N_NODES + BM - 1) / BM)     // 1563
#define GRID_Y 111

__device__ __forceinline__ void load_a_chunk(uint32_t s_as, int mt, int c, int tid) {
    #pragma unroll
    for (int i = 0; i < 2; i++) {
        int idx = tid + i * 256;         // 0..511
        int r = idx >> 3;                // 0..63
        int q = idx & 7;                 // 8 x 16B per 64-half row
        int m = mt * BM + r;
        const __half* src = g_Xs + (size_t)(m < N_NODES ? m : 0) * KSP + c * BKC + q * 8;
        cp16(s_as + (r * AS_ROW + q * 8) * 2, src, (m < N_NODES) ? 16 : 0);
    }
}

__global__ void __launch_bounds__(256, 3) node_mma_kernel(const float* __restrict__ b1) {
    extern __shared__ char smem[];
    const uint32_t s_ws = smem_u32(smem);
    const uint32_t s_as = s_ws + WS_BYTES;

    const int tid  = threadIdx.x;
    const int lane = tid & 31;
    const int wid  = tid >> 5;
    const int wm   = wid & 1;        // 0..1: 32-row slice
    const int wn   = wid >> 1;       // 0..3: 32-col slice
    const int n0   = blockIdx.x * BN;
    const int lane15 = lane & 15;
    const int ksel   = (lane >> 4) << 3;

    // Load resident W slice [128 K-rows, 128 cols]
    #pragma unroll
    for (int i = 0; i < 8; i++) {
        int idx = tid + i * 256;      // < 2048
        int r = idx >> 4;             // K-row 0..127
        int q = idx & 15;             // 16 x 16B per 128-half row
        cp16(s_ws + (r * WS_ROW + q * 8) * 2,
             g_Ws + (size_t)r * CTOT + n0 + q * 8, 16);
    }
    load_a_chunk(s_as, blockIdx.y, 0, tid);
    cp_commit();

    const bool bias = (n0 < HIDDEN);
    int gc = 0;

    for (int mt = blockIdx.y; mt < NMT; mt += GRID_Y) {
        float acc[2][4][4];
        #pragma unroll
        for (int mi = 0; mi < 2; mi++)
            #pragma unroll
            for (int ni = 0; ni < 4; ni++)
                #pragma unroll
                for (int t = 0; t < 4; t++) acc[mi][ni][t] = 0.0f;

        for (int c = 0; c < NCHUNK; c++, gc++) {
            cp_wait<0>();
            __syncthreads();
            if (c + 1 < NCHUNK) {
                load_a_chunk(s_as + ((gc + 1) & 1) * AS_BUF_BYTES, mt, c + 1, tid);
                cp_commit();
            } else if (mt + GRID_Y < NMT) {
                load_a_chunk(s_as + ((gc + 1) & 1) * AS_BUF_BYTES, mt + GRID_Y, 0, tid);
                cp_commit();
            }
            const uint32_t abuf = s_as + (gc & 1) * AS_BUF_BYTES;
            const int wrow = (c & 1) * BKC;   // dedup: chunks 2,3 reuse W rows 0..127
            #pragma unroll
            for (int ks = 0; ks < 4; ks++) {
                uint32_t Af[2][4], Bf[2][4];
                #pragma unroll
                for (int mi = 0; mi < 2; mi++) {
                    uint32_t addr = abuf +
                        ((wm * 32 + mi * 16 + lane15) * AS_ROW + ks * 16 + ksel) * 2;
                    ldsm_x4(Af[mi], addr);
                }
                #pragma unroll
                for (int np = 0; np < 2; np++) {
                    uint32_t addr = s_ws +
                        ((wrow + ks * 16 + lane15) * WS_ROW + wn * 32 + np * 16 + ksel) * 2;
                    ldsm_x4_t(Bf[np], addr);
                }
                #pragma unroll
                for (int mi = 0; mi < 2; mi++)
                    #pragma unroll
                    for (int np = 0; np < 2; np++) {
                        mma16816(acc[mi][np * 2 + 0], Af[mi], Bf[np][0], Bf[np][1]);
                        mma16816(acc[mi][np * 2 + 1], Af[mi], Bf[np][2], Bf[np][3]);
                    }
            }
        }

        const int m_base = mt * BM + wm * 32;
        #pragma unroll
        for (int ni = 0; ni < 4; ni++) {
            int col = n0 + wn * 32 + ni * 8 + ((lane & 3) << 1);
            float bb0 = 0.f, bb1 = 0.f;
            if (bias) { bb0 = b1[col]; bb1 = b1[col + 1]; }
            #pragma unroll
            for (int mi = 0; mi < 2; mi++) {
                int r0 = m_base + mi * 16 + (lane >> 2);
                float* a = acc[mi][ni];
                if (r0 < N_NODES)
                    *(__half2*)(g_Ch + (size_t)r0 * CTOT + col) =
                        __floats2half2_rn(a[0] + bb0, a[1] + bb1);
                int r1 = r0 + 8;
                if (r1 < N_NODES)
                    *(__half2*)(g_Ch + (size_t)r1 * CTOT + col) =
                        __floats2half2_rn(a[2] + bb0, a[3] + bb1);
            }
        }
    }
}

// ---------------------------------------------------------------------------
// Edge kernel: register-gather, 4 edges/warp-iter. Round-12 winner plus:
//  - LN apply refactored: t = fma(z, rstd, -mean*rstd); y = fma(t, ga, be)
//    (saves the per-element subtract+mul chain, ~7 instr/edge)
//  - direct predicated output stores from lanes 0/16 (removes 8 shfl/4 edges)
// ---------------------------------------------------------------------------
__global__ void __launch_bounds__(256, 2) edge_kernel(
    const float* __restrict__ polar,
    const void*  __restrict__ srcv,
    const void*  __restrict__ dstv,
    const float* __restrict__ W1,
    const float* __restrict__ gamma,
    const float* __restrict__ beta,
    const float* __restrict__ W2,
    const float* __restrict__ b2,
    float* __restrict__ out)
{
    const int lane = threadIdx.x & 31;
    const int warp = (blockIdx.x * blockDim.x + threadIdx.x) >> 5;
    const int nwarps = (gridDim.x * blockDim.x) >> 5;
    const int j0 = lane * 8;
    const unsigned FULL = 0xFFFFFFFFu;

    float wp0[8], wp1[8], ga[8], be[8], w2a[8], w2b[8];
    #pragma unroll
    for (int i = 0; i < 8; i++) {
        int j = j0 + i;
        wp0[i] = W1[(size_t)128 * HIDDEN + j];
        wp1[i] = W1[(size_t)129 * HIDDEN + j];
        ga[i]  = gamma[j];
        be[i]  = beta[j];
        w2a[i] = W2[j * 2 + 0];
        w2b[i] = W2[j * 2 + 1];
    }
    const float bias0 = b2[0], bias1 = b2[1];
    const float mybias = (lane < 16) ? bias0 : bias1;
    const bool writer = ((lane & 15) == 0);     // lanes 0 and 16
    const int  wsel   = lane >> 4;              // 0 -> out0, 1 -> out1

    const bool is64 = (g_idx64 != 0);
    const long long* src64 = (const long long*)srcv;
    const long long* dst64 = (const long long*)dstv;
    const int*       src32 = (const int*)srcv;
    const int*       dst32 = (const int*)dstv;

    for (int e = warp * 4; e < E_EDGES; e += 4 * nwarps) {
        int s[4], d[4];
        if (is64) {
            longlong2 S0 = *(const longlong2*)(src64 + e);
            longlong2 S1 = *(const longlong2*)(src64 + e + 2);
            longlong2 D0 = *(const longlong2*)(dst64 + e);
            longlong2 D1 = *(const longlong2*)(dst64 + e + 2);
            s[0] = (int)S0.x; s[1] = (int)S0.y; s[2] = (int)S1.x; s[3] = (int)S1.y;
            d[0] = (int)D0.x; d[1] = (int)D0.y; d[2] = (int)D1.x; d[3] = (int)D1.y;
        } else {
            int4 S = *(const int4*)(src32 + e);
            int4 D = *(const int4*)(dst32 + e);
            s[0] = S.x; s[1] = S.y; s[2] = S.z; s[3] = S.w;
            d[0] = D.x; d[1] = D.y; d[2] = D.z; d[3] = D.w;
        }
        float4 p01 = *(const float4*)(polar + (size_t)e * 2);
        float4 p23 = *(const float4*)(polar + (size_t)e * 2 + 4);
        float px[4] = {p01.x, p01.z, p23.x, p23.z};
        float py[4] = {p01.y, p01.w, p23.y, p23.w};

        uint4 va[4], vb[4];
        #pragma unroll
        for (int ei = 0; ei < 4; ei++) {
            va[ei] = *(const uint4*)(g_Ch + (size_t)s[ei] * CTOT + j0);
            vb[ei] = *(const uint4*)(g_Ch + (size_t)d[ei] * CTOT + HIDDEN + j0);
        }

        #pragma unroll
        for (int ei = 0; ei < 4; ei++) {
            const __half2* ah = reinterpret_cast<const __half2*>(&va[ei]);
            const __half2* bh = reinterpret_cast<const __half2*>(&vb[ei]);
            float2 zp0 = __half22float2(__hadd2(ah[0], bh[0]));
            float2 zp1 = __half22float2(__hadd2(ah[1], bh[1]));
            float2 zp2 = __half22float2(__hadd2(ah[2], bh[2]));
            float2 zp3 = __half22float2(__hadd2(ah[3], bh[3]));
            float z[8] = {zp0.x, zp0.y, zp1.x, zp1.y, zp2.x, zp2.y, zp3.x, zp3.y};
            #pragma unroll
            for (int i = 0; i < 8; i++)
                z[i] = fmaf(px[ei], wp0[i], fmaf(py[ei], wp1[i], z[i]));

            float s1v = 0.f, s2v = 0.f;
            #pragma unroll
            for (int i = 0; i < 8; i++) {
                s1v += z[i];
                s2v = fmaf(z[i], z[i], s2v);
            }
            // paired reduction: split (s1,s2) across lane halves
            s1v += __shfl_xor_sync(FULL, s1v, 16);
            s2v += __shfl_xor_sync(FULL, s2v, 16);
            float ms = (lane < 16) ? s1v : s2v;
            #pragma unroll
            for (int o2 = 8; o2 > 0; o2 >>= 1)
                ms += __shfl_xor_sync(FULL, ms, o2);
            const float s1t = __shfl_sync(FULL, ms, lane & 15);
            const float s2t = __shfl_sync(FULL, ms, (lane & 15) | 16);

            const float mean = s1t * (1.0f / 256.0f);
            const float var  = fmaf(-mean, mean, s2t * (1.0f / 256.0f));
            const float rstd = rsqrtf(var + 1e-5f);
            const float nmr  = -mean * rstd;

            float acc0 = 0.f, acc1 = 0.f;
            #pragma unroll
            for (int i = 0; i < 8; i++) {
                float t = fmaf(z[i], rstd, nmr);
                float y = fmaf(t, ga[i], be[i]);
                y = fmaxf(y, 0.0f);
                acc0 = fmaf(y, w2a[i], acc0);
                acc1 = fmaf(y, w2b[i], acc1);
            }
            // paired reduction for (acc0, acc1)
            acc0 += __shfl_xor_sync(FULL, acc0, 16);
            acc1 += __shfl_xor_sync(FULL, acc1, 16);
            float av = (lane < 16) ? acc0 : acc1;
            #pragma unroll
            for (int o2 = 8; o2 > 0; o2 >>= 1)
                av += __shfl_xor_sync(FULL, av, o2);
            // lanes 0 / 16 hold out0 / out1 for edge e+ei: store directly
            if (writer)
                out[(size_t)(e + ei) * 2 + wsel] = av + mybias;
        }
    }
}

// ---------------------------------------------------------------------------
// Launch
// ---------------------------------------------------------------------------
extern "C" void kernel_launch(void* const* d_in, const int* in_sizes, int n_in,
                              void* d_out, int out_size) {
    const float* h     = (const float*)d_in[0];
    const float* cls   = (const float*)d_in[1];
    const float* polar = (const float*)d_in[2];
    const void*  src   = d_in[3];
    const void*  dst   = d_in[4];
    const float* W1    = (const float*)d_in[5];
    const float* b1    = (const float*)d_in[6];
    const float* gamma = (const float*)d_in[7];
    const float* beta  = (const float*)d_in[8];
    const float* W2    = (const float*)d_in[9];
    const float* b2    = (const float*)d_in[10];
    float* out = (float*)d_out;

    (void)in_sizes; (void)n_in; (void)out_size;

    cudaFuncSetAttribute(node_mma_kernel,
                         cudaFuncAttributeMaxDynamicSharedMemorySize, GEMM_SMEM);

    detect_idx_kernel<<<1, 1>>>(src);

    {
        int total = N_NODES * XDIM;
        prep_x_kernel<<<(total + 255) / 256, 256>>>(h, cls);
    }
    {
        int total = XDIM * CTOT;
        prep_w_kernel<<<(total + 255) / 256, 256>>>(W1);
    }
    {
        dim3 grid(CTOT / BN, GRID_Y);   // (4, 111) = 444 CTAs = 148 SMs x 3
        node_mma_kernel<<<grid, 256, GEMM_SMEM>>>(b1);
    }
    {
        edge_kernel<<<1184, 256>>>(polar, src, dst, W1, gamma, beta, W2, b2, out);
    }
}

// round 14
// speedup vs baseline: 1.6060x; 1.0463x over previous
#include <cuda_runtime.h>
#include <cuda_fp16.h>
#include <cstdint>

// Problem constants
#define N_NODES 100000
#define E_EDGES 1000000
#define H_DIMC  124
#define XDIM    128
#define HIDDEN  256
#define CTOT    512     // A (256) || B (256)
#define KSP     256     // split-K: [hi | lo]

// ---------------------------------------------------------------------------
// Static device scratch
// ---------------------------------------------------------------------------
__device__ __half g_Xs[(size_t)N_NODES * KSP];   // [N,256] fp16 split X (51MB)
__device__ __half g_Ws[(size_t)XDIM * CTOT];     // [128,512] fp16 = hi(Wg)
__device__ __half g_Ch[(size_t)N_NODES * CTOT];  // [N,512] fp16 = [A|B], b1 folded into A
__device__ int    g_idx64;

// ---------------------------------------------------------------------------
// PTX helpers
// ---------------------------------------------------------------------------
__device__ __forceinline__ uint32_t smem_u32(const void* p) {
    return (uint32_t)__cvta_generic_to_shared(p);
}
__device__ __forceinline__ void ldsm_x4(uint32_t (&r)[4], uint32_t addr) {
    asm volatile("ldmatrix.sync.aligned.m8n8.x4.shared.b16 {%0,%1,%2,%3}, [%4];"
                 : "=r"(r[0]), "=r"(r[1]), "=r"(r[2]), "=r"(r[3]) : "r"(addr));
}
__device__ __forceinline__ void ldsm_x4_t(uint32_t* r, uint32_t addr) {
    asm volatile("ldmatrix.sync.aligned.m8n8.x4.trans.shared.b16 {%0,%1,%2,%3}, [%4];"
                 : "=r"(r[0]), "=r"(r[1]), "=r"(r[2]), "=r"(r[3]) : "r"(addr));
}
__device__ __forceinline__ void mma16816(float (&d)[4], const uint32_t (&a)[4],
                                         uint32_t b0, uint32_t b1) {
    asm volatile("mma.sync.aligned.m16n8k16.row.col.f32.f16.f16.f32 "
                 "{%0,%1,%2,%3}, {%4,%5,%6,%7}, {%8,%9}, {%0,%1,%2,%3};"
                 : "+f"(d[0]), "+f"(d[1]), "+f"(d[2]), "+f"(d[3])
                 : "r"(a[0]), "r"(a[1]), "r"(a[2]), "r"(a[3]), "r"(b0), "r"(b1));
}
__device__ __forceinline__ void cp16(uint32_t dst, const void* src, int sz) {
    asm volatile("cp.async.cg.shared.global [%0], [%1], 16, %2;"
                 :: "r"(dst), "l"(src), "r"(sz));
}
__device__ __forceinline__ void cp_commit() { asm volatile("cp.async.commit_group;"); }
template <int K>
__device__ __forceinline__ void cp_wait() { asm volatile("cp.async.wait_group %0;" :: "n"(K)); }

// ---------------------------------------------------------------------------
// Index width detection
// ---------------------------------------------------------------------------
__global__ void detect_idx_kernel(const void* __restrict__ srcv) {
    const unsigned long long* p = (const unsigned long long*)srcv;
    int ok = 1;
    #pragma unroll
    for (int i = 0; i < 8; i++)
        if (p[i] >= (unsigned long long)N_NODES) ok = 0;
    g_idx64 = ok;
}

// ---------------------------------------------------------------------------
// Pack Xs = [hi(x) | lo(x)] where x = [h | softmax(cls)]
// ---------------------------------------------------------------------------
__global__ void prep_x_kernel(const float* __restrict__ h,
                              const float* __restrict__ cls) {
    int idx = blockIdx.x * blockDim.x + threadIdx.x;
    if (idx >= N_NODES * XDIM) return;
    int n = idx >> 7;
    int j = idx & 127;
    float v;
    if (j < H_DIMC) {
        v = h[(size_t)n * H_DIMC + j];
    } else {
        int c = j - H_DIMC;
        float4 l = *(const float4*)(cls + (size_t)n * 4);
        float m = fmaxf(fmaxf(l.x, l.y), fmaxf(l.z, l.w));
        float e0 = expf(l.x - m), e1 = expf(l.y - m);
        float e2 = expf(l.z - m), e3 = expf(l.w - m);
        float inv = 1.0f / (e0 + e1 + e2 + e3);
        float ec = (c == 0) ? e0 : (c == 1) ? e1 : (c == 2) ? e2 : e3;
        v = ec * inv;
    }
    __half hi = __float2half_rn(v);
    __half lo = __float2half_rn(v - __half2float(hi));
    size_t base = (size_t)n * KSP;
    g_Xs[base + j]       = hi;
    g_Xs[base + 128 + j] = lo;
}

// ---------------------------------------------------------------------------
// Pack Ws[k][c] = hi(Wg[k][c])
// ---------------------------------------------------------------------------
__global__ void prep_w_kernel(const float* __restrict__ W1) {
    int idx = blockIdx.x * blockDim.x + threadIdx.x;
    if (idx >= XDIM * CTOT) return;
    int k = idx >> 9;
    int c = idx & 511;
    float w = (c < HIDDEN) ? W1[(size_t)k * HIDDEN + c]
                           : W1[(size_t)(130 + k) * HIDDEN + (c - HIDDEN)];
    g_Ws[(size_t)k * CTOT + c] = __float2half_rn(w);
}

// ---------------------------------------------------------------------------
// Tensor-core node GEMM: C[N,512] = Xs[N,256] @ [Whi;Whi] (+b1 on cols<256)
// BM=64, BN=128, 8 warps (2M x 4N), warp tile 32x32.
// NEW: B (weight) MMA fragments hoisted into registers ONCE before the mt
// loop (they are invariant: W is CTA-resident, 2 chunk parities after dedup).
// Inner loop = A ldsm + MMA only -> B-side L1/smem traffic eliminated.
// ---------------------------------------------------------------------------
#define BM 64
#define BN 128
#define BKC 64
#define NCHUNK (KSP / BKC)               // 4
#define WS_ROW 136
#define AS_ROW 72
#define WS_BYTES (128 * WS_ROW * 2)       // 34816
#define AS_BUF_BYTES (BM * AS_ROW * 2)    // 9216
#define GEMM_SMEM (WS_BYTES + 2 * AS_BUF_BYTES)  // 53248
#define NMT ((N_NODES + BM - 1) / BM)     // 1563
#define GRID_Y 74

__device__ __forceinline__ void load_a_chunk(uint32_t s_as, int mt, int c, int tid) {
    #pragma unroll
    for (int i = 0; i < 2; i++) {
        int idx = tid + i * 256;         // 0..511
        int r = idx >> 3;                // 0..63
        int q = idx & 7;                 // 8 x 16B per 64-half row
        int m = mt * BM + r;
        const __half* src = g_Xs + (size_t)(m < N_NODES ? m : 0) * KSP + c * BKC + q * 8;
        cp16(s_as + (r * AS_ROW + q * 8) * 2, src, (m < N_NODES) ? 16 : 0);
    }
}

__global__ void __launch_bounds__(256, 2) node_mma_kernel(const float* __restrict__ b1) {
    extern __shared__ char smem[];
    const uint32_t s_ws = smem_u32(smem);
    const uint32_t s_as = s_ws + WS_BYTES;

    const int tid  = threadIdx.x;
    const int lane = tid & 31;
    const int wid  = tid >> 5;
    const int wm   = wid & 1;        // 0..1: 32-row slice
    const int wn   = wid >> 1;       // 0..3: 32-col slice
    const int n0   = blockIdx.x * BN;
    const int lane15 = lane & 15;
    const int ksel   = (lane >> 4) << 3;

    // Load resident W slice [128 K-rows, 128 cols] + first A chunk
    #pragma unroll
    for (int i = 0; i < 8; i++) {
        int idx = tid + i * 256;      // < 2048
        int r = idx >> 4;             // K-row 0..127
        int q = idx & 15;             // 16 x 16B per 128-half row
        cp16(s_ws + (r * WS_ROW + q * 8) * 2,
             g_Ws + (size_t)r * CTOT + n0 + q * 8, 16);
    }
    load_a_chunk(s_as, blockIdx.y, 0, tid);
    cp_commit();
    cp_wait<0>();
    __syncthreads();

    // Hoist ALL B fragments into registers: Breg[parity][ks][np][4].
    // Invariant across the whole mt loop (nobody rewrites s_ws).
    uint32_t Breg[2][4][2][4];
    #pragma unroll
    for (int cp = 0; cp < 2; cp++)
        #pragma unroll
        for (int ks = 0; ks < 4; ks++)
            #pragma unroll
            for (int np = 0; np < 2; np++) {
                uint32_t addr = s_ws +
                    ((cp * BKC + ks * 16 + lane15) * WS_ROW + wn * 32 + np * 16 + ksel) * 2;
                ldsm_x4_t(Breg[cp][ks][np], addr);
            }

    const bool bias = (n0 < HIDDEN);
    int gc = 0;

    for (int mt = blockIdx.y; mt < NMT; mt += GRID_Y) {
        float acc[2][4][4];
        #pragma unroll
        for (int mi = 0; mi < 2; mi++)
            #pragma unroll
            for (int ni = 0; ni < 4; ni++)
                #pragma unroll
                for (int t = 0; t < 4; t++) acc[mi][ni][t] = 0.0f;

        for (int c = 0; c < NCHUNK; c++, gc++) {
            cp_wait<0>();
            __syncthreads();
            if (c + 1 < NCHUNK) {
                load_a_chunk(s_as + ((gc + 1) & 1) * AS_BUF_BYTES, mt, c + 1, tid);
                cp_commit();
            } else if (mt + GRID_Y < NMT) {
                load_a_chunk(s_as + ((gc + 1) & 1) * AS_BUF_BYTES, mt + GRID_Y, 0, tid);
                cp_commit();
            }
            const uint32_t abuf = s_as + (gc & 1) * AS_BUF_BYTES;
            const int cp = c & 1;
            #pragma unroll
            for (int ks = 0; ks < 4; ks++) {
                uint32_t Af[2][4];
                #pragma unroll
                for (int mi = 0; mi < 2; mi++) {
                    uint32_t addr = abuf +
                        ((wm * 32 + mi * 16 + lane15) * AS_ROW + ks * 16 + ksel) * 2;
                    ldsm_x4(Af[mi], addr);
                }
                #pragma unroll
                for (int mi = 0; mi < 2; mi++)
                    #pragma unroll
                    for (int np = 0; np < 2; np++) {
                        mma16816(acc[mi][np * 2 + 0], Af[mi],
                                 Breg[cp][ks][np][0], Breg[cp][ks][np][1]);
                        mma16816(acc[mi][np * 2 + 1], Af[mi],
                                 Breg[cp][ks][np][2], Breg[cp][ks][np][3]);
                    }
            }
        }

        const int m_base = mt * BM + wm * 32;
        #pragma unroll
        for (int ni = 0; ni < 4; ni++) {
            int col = n0 + wn * 32 + ni * 8 + ((lane & 3) << 1);
            float bb0 = 0.f, bb1 = 0.f;
            if (bias) { bb0 = b1[col]; bb1 = b1[col + 1]; }
            #pragma unroll
            for (int mi = 0; mi < 2; mi++) {
                int r0 = m_base + mi * 16 + (lane >> 2);
                float* a = acc[mi][ni];
                if (r0 < N_NODES)
                    *(__half2*)(g_Ch + (size_t)r0 * CTOT + col) =
                        __floats2half2_rn(a[0] + bb0, a[1] + bb1);
                int r1 = r0 + 8;
                if (r1 < N_NODES)
                    *(__half2*)(g_Ch + (size_t)r1 * CTOT + col) =
                        __floats2half2_rn(a[2] + bb0, a[3] + bb1);
            }
        }
    }
}

// ---------------------------------------------------------------------------
// Edge kernel (UNCHANGED from round 13 winner, protected)
// ---------------------------------------------------------------------------
__global__ void __launch_bounds__(256, 2) edge_kernel(
    const float* __restrict__ polar,
    const void*  __restrict__ srcv,
    const void*  __restrict__ dstv,
    const float* __restrict__ W1,
    const float* __restrict__ gamma,
    const float* __restrict__ beta,
    const float* __restrict__ W2,
    const float* __restrict__ b2,
    float* __restrict__ out)
{
    const int lane = threadIdx.x & 31;
    const int warp = (blockIdx.x * blockDim.x + threadIdx.x) >> 5;
    const int nwarps = (gridDim.x * blockDim.x) >> 5;
    const int j0 = lane * 8;
    const unsigned FULL = 0xFFFFFFFFu;

    float wp0[8], wp1[8], ga[8], be[8], w2a[8], w2b[8];
    #pragma unroll
    for (int i = 0; i < 8; i++) {
        int j = j0 + i;
        wp0[i] = W1[(size_t)128 * HIDDEN + j];
        wp1[i] = W1[(size_t)129 * HIDDEN + j];
        ga[i]  = gamma[j];
        be[i]  = beta[j];
        w2a[i] = W2[j * 2 + 0];
        w2b[i] = W2[j * 2 + 1];
    }
    const float bias0 = b2[0], bias1 = b2[1];
    const float mybias = (lane < 16) ? bias0 : bias1;
    const bool writer = ((lane & 15) == 0);
    const int  wsel   = lane >> 4;

    const bool is64 = (g_idx64 != 0);
    const long long* src64 = (const long long*)srcv;
    const long long* dst64 = (const long long*)dstv;
    const int*       src32 = (const int*)srcv;
    const int*       dst32 = (const int*)dstv;

    for (int e = warp * 4; e < E_EDGES; e += 4 * nwarps) {
        int s[4], d[4];
        if (is64) {
            longlong2 S0 = *(const longlong2*)(src64 + e);
            longlong2 S1 = *(const longlong2*)(src64 + e + 2);
            longlong2 D0 = *(const longlong2*)(dst64 + e);
            longlong2 D1 = *(const longlong2*)(dst64 + e + 2);
            s[0] = (int)S0.x; s[1] = (int)S0.y; s[2] = (int)S1.x; s[3] = (int)S1.y;
            d[0] = (int)D0.x; d[1] = (int)D0.y; d[2] = (int)D1.x; d[3] = (int)D1.y;
        } else {
            int4 S = *(const int4*)(src32 + e);
            int4 D = *(const int4*)(dst32 + e);
            s[0] = S.x; s[1] = S.y; s[2] = S.z; s[3] = S.w;
            d[0] = D.x; d[1] = D.y; d[2] = D.z; d[3] = D.w;
        }
        float4 p01 = *(const float4*)(polar + (size_t)e * 2);
        float4 p23 = *(const float4*)(polar + (size_t)e * 2 + 4);
        float px[4] = {p01.x, p01.z, p23.x, p23.z};
        float py[4] = {p01.y, p01.w, p23.y, p23.w};

        uint4 va[4], vb[4];
        #pragma unroll
        for (int ei = 0; ei < 4; ei++) {
            va[ei] = *(const uint4*)(g_Ch + (size_t)s[ei] * CTOT + j0);
            vb[ei] = *(const uint4*)(g_Ch + (size_t)d[ei] * CTOT + HIDDEN + j0);
        }

        #pragma unroll
        for (int ei = 0; ei < 4; ei++) {
            const __half2* ah = reinterpret_cast<const __half2*>(&va[ei]);
            const __half2* bh = reinterpret_cast<const __half2*>(&vb[ei]);
            float2 zp0 = __half22float2(__hadd2(ah[0], bh[0]));
            float2 zp1 = __half22float2(__hadd2(ah[1], bh[1]));
            float2 zp2 = __half22float2(__hadd2(ah[2], bh[2]));
            float2 zp3 = __half22float2(__hadd2(ah[3], bh[3]));
            float z[8] = {zp0.x, zp0.y, zp1.x, zp1.y, zp2.x, zp2.y, zp3.x, zp3.y};
            #pragma unroll
            for (int i = 0; i < 8; i++)
                z[i] = fmaf(px[ei], wp0[i], fmaf(py[ei], wp1[i], z[i]));

            float s1v = 0.f, s2v = 0.f;
            #pragma unroll
            for (int i = 0; i < 8; i++) {
                s1v += z[i];
                s2v = fmaf(z[i], z[i], s2v);
            }
            s1v += __shfl_xor_sync(FULL, s1v, 16);
            s2v += __shfl_xor_sync(FULL, s2v, 16);
            float ms = (lane < 16) ? s1v : s2v;
            #pragma unroll
            for (int o2 = 8; o2 > 0; o2 >>= 1)
                ms += __shfl_xor_sync(FULL, ms, o2);
            const float s1t = __shfl_sync(FULL, ms, lane & 15);
            const float s2t = __shfl_sync(FULL, ms, (lane & 15) | 16);

            const float mean = s1t * (1.0f / 256.0f);
            const float var  = fmaf(-mean, mean, s2t * (1.0f / 256.0f));
            const float rstd = rsqrtf(var + 1e-5f);
            const float nmr  = -mean * rstd;

            float acc0 = 0.f, acc1 = 0.f;
            #pragma unroll
            for (int i = 0; i < 8; i++) {
                float t = fmaf(z[i], rstd, nmr);
                float y = fmaf(t, ga[i], be[i]);
                y = fmaxf(y, 0.0f);
                acc0 = fmaf(y, w2a[i], acc0);
                acc1 = fmaf(y, w2b[i], acc1);
            }
            acc0 += __shfl_xor_sync(FULL, acc0, 16);
            acc1 += __shfl_xor_sync(FULL, acc1, 16);
            float av = (lane < 16) ? acc0 : acc1;
            #pragma unroll
            for (int o2 = 8; o2 > 0; o2 >>= 1)
                av += __shfl_xor_sync(FULL, av, o2);
            if (writer)
                out[(size_t)(e + ei) * 2 + wsel] = av + mybias;
        }
    }
}

// ---------------------------------------------------------------------------
// Launch
// ---------------------------------------------------------------------------
extern "C" void kernel_launch(void* const* d_in, const int* in_sizes, int n_in,
                              void* d_out, int out_size) {
    const float* h     = (const float*)d_in[0];
    const float* cls   = (const float*)d_in[1];
    const float* polar = (const float*)d_in[2];
    const void*  src   = d_in[3];
    const void*  dst   = d_in[4];
    const float* W1    = (const float*)d_in[5];
    const float* b1    = (const float*)d_in[6];
    const float* gamma = (const float*)d_in[7];
    const float* beta  = (const float*)d_in[8];
    const float* W2    = (const float*)d_in[9];
    const float* b2    = (const float*)d_in[10];
    float* out = (float*)d_out;

    (void)in_sizes; (void)n_in; (void)out_size;

    cudaFuncSetAttribute(node_mma_kernel,
                         cudaFuncAttributeMaxDynamicSharedMemorySize, GEMM_SMEM);

    detect_idx_kernel<<<1, 1>>>(src);

    {
        int total = N_NODES * XDIM;
        prep_x_kernel<<<(total + 255) / 256, 256>>>(h, cls);
    }
    {
        int total = XDIM * CTOT;
        prep_w_kernel<<<(total + 255) / 256, 256>>>(W1);
    }
    {
        dim3 grid(CTOT / BN, GRID_Y);   // (4, 74) = 296 CTAs -> 2 CTAs/SM
        node_mma_kernel<<<grid, 256, GEMM_SMEM>>>(b1);
    }
    {
        edge_kernel<<<1184, 256>>>(polar, src, dst, W1, gamma, beta, W2, b2, out);
    }
}

// round 15
// speedup vs baseline: 1.7729x; 1.1039x over previous
#include <cuda_runtime.h>
#include <cuda_fp16.h>
#include <cstdint>

// Problem constants
#define N_NODES 100000
#define E_EDGES 1000000
#define H_DIMC  124
#define XDIM    128
#define HIDDEN  256
#define CTOT    512     // A (256) || B (256)
#define KSP     128     // single fp16 hi term (lo split dropped; +2.8e-4 RMS)

// ---------------------------------------------------------------------------
// Static device scratch
// ---------------------------------------------------------------------------
__device__ __half g_Xs[(size_t)N_NODES * KSP];   // [N,128] fp16 = hi(x) (26MB)
__device__ __half g_Ws[(size_t)XDIM * CTOT];     // [128,512] fp16 = hi(Wg)
__device__ __half g_Ch[(size_t)N_NODES * CTOT];  // [N,512] fp16 = [A|B], b1 folded into A
__device__ int    g_idx64;

// ---------------------------------------------------------------------------
// PTX helpers
// ---------------------------------------------------------------------------
__device__ __forceinline__ uint32_t smem_u32(const void* p) {
    return (uint32_t)__cvta_generic_to_shared(p);
}
__device__ __forceinline__ void ldsm_x4(uint32_t (&r)[4], uint32_t addr) {
    asm volatile("ldmatrix.sync.aligned.m8n8.x4.shared.b16 {%0,%1,%2,%3}, [%4];"
                 : "=r"(r[0]), "=r"(r[1]), "=r"(r[2]), "=r"(r[3]) : "r"(addr));
}
__device__ __forceinline__ void ldsm_x4_t(uint32_t* r, uint32_t addr) {
    asm volatile("ldmatrix.sync.aligned.m8n8.x4.trans.shared.b16 {%0,%1,%2,%3}, [%4];"
                 : "=r"(r[0]), "=r"(r[1]), "=r"(r[2]), "=r"(r[3]) : "r"(addr));
}
__device__ __forceinline__ void mma16816(float (&d)[4], const uint32_t (&a)[4],
                                         uint32_t b0, uint32_t b1) {
    asm volatile("mma.sync.aligned.m16n8k16.row.col.f32.f16.f16.f32 "
                 "{%0,%1,%2,%3}, {%4,%5,%6,%7}, {%8,%9}, {%0,%1,%2,%3};"
                 : "+f"(d[0]), "+f"(d[1]), "+f"(d[2]), "+f"(d[3])
                 : "r"(a[0]), "r"(a[1]), "r"(a[2]), "r"(a[3]), "r"(b0), "r"(b1));
}
__device__ __forceinline__ void cp16(uint32_t dst, const void* src, int sz) {
    asm volatile("cp.async.cg.shared.global [%0], [%1], 16, %2;"
                 :: "r"(dst), "l"(src), "r"(sz));
}
__device__ __forceinline__ void cp_commit() { asm volatile("cp.async.commit_group;"); }
template <int K>
__device__ __forceinline__ void cp_wait() { asm volatile("cp.async.wait_group %0;" :: "n"(K)); }

// ---------------------------------------------------------------------------
// Index width detection
// ---------------------------------------------------------------------------
__global__ void detect_idx_kernel(const void* __restrict__ srcv) {
    const unsigned long long* p = (const unsigned long long*)srcv;
    int ok = 1;
    #pragma unroll
    for (int i = 0; i < 8; i++)
        if (p[i] >= (unsigned long long)N_NODES) ok = 0;
    g_idx64 = ok;
}

// ---------------------------------------------------------------------------
// Pack Xs = hi(x) where x = [h | softmax(cls)]
// ---------------------------------------------------------------------------
__global__ void prep_x_kernel(const float* __restrict__ h,
                              const float* __restrict__ cls) {
    int idx = blockIdx.x * blockDim.x + threadIdx.x;
    if (idx >= N_NODES * XDIM) return;
    int n = idx >> 7;
    int j = idx & 127;
    float v;
    if (j < H_DIMC) {
        v = h[(size_t)n * H_DIMC + j];
    } else {
        int c = j - H_DIMC;
        float4 l = *(const float4*)(cls + (size_t)n * 4);
        float m = fmaxf(fmaxf(l.x, l.y), fmaxf(l.z, l.w));
        float e0 = expf(l.x - m), e1 = expf(l.y - m);
        float e2 = expf(l.z - m), e3 = expf(l.w - m);
        float inv = 1.0f / (e0 + e1 + e2 + e3);
        float ec = (c == 0) ? e0 : (c == 1) ? e1 : (c == 2) ? e2 : e3;
        v = ec * inv;
    }
    g_Xs[(size_t)n * KSP + j] = __float2half_rn(v);
}

// ---------------------------------------------------------------------------
// Pack Ws[k][c] = hi(Wg[k][c])
// ---------------------------------------------------------------------------
__global__ void prep_w_kernel(const float* __restrict__ W1) {
    int idx = blockIdx.x * blockDim.x + threadIdx.x;
    if (idx >= XDIM * CTOT) return;
    int k = idx >> 9;
    int c = idx & 511;
    float w = (c < HIDDEN) ? W1[(size_t)k * HIDDEN + c]
                           : W1[(size_t)(130 + k) * HIDDEN + (c - HIDDEN)];
    g_Ws[(size_t)k * CTOT + c] = __float2half_rn(w);
}

// ---------------------------------------------------------------------------
// Tensor-core node GEMM: C[N,512] = Xs[N,128] @ Whi[128,512] (+b1 on cols<256)
// BM=64, BN=128, 8 warps (2M x 4N), warp tile 32x32. K=128 -> 2 chunks.
// B fragments register-resident (invariant across the persistent mt loop).
// ---------------------------------------------------------------------------
#define BM 64
#define BN 128
#define BKC 64
#define NCHUNK (KSP / BKC)               // 2
#define WS_ROW 136
#define AS_ROW 72
#define WS_BYTES (128 * WS_ROW * 2)       // 34816
#define AS_BUF_BYTES (BM * AS_ROW * 2)    // 9216
#define GEMM_SMEM (WS_BYTES + 2 * AS_BUF_BYTES)  // 53248
#define NMT ((N_NODES + BM - 1) / BM)     // 1563
#define GRID_Y 74

__device__ __forceinline__ void load_a_chunk(uint32_t s_as, int mt, int c, int tid) {
    #pragma unroll
    for (int i = 0; i < 2; i++) {
        int idx = tid + i * 256;         // 0..511
        int r = idx >> 3;                // 0..63
        int q = idx & 7;                 // 8 x 16B per 64-half row
        int m = mt * BM + r;
        const __half* src = g_Xs + (size_t)(m < N_NODES ? m : 0) * KSP + c * BKC + q * 8;
        cp16(s_as + (r * AS_ROW + q * 8) * 2, src, (m < N_NODES) ? 16 : 0);
    }
}

__global__ void __launch_bounds__(256, 2) node_mma_kernel(const float* __restrict__ b1) {
    extern __shared__ char smem[];
    const uint32_t s_ws = smem_u32(smem);
    const uint32_t s_as = s_ws + WS_BYTES;

    const int tid  = threadIdx.x;
    const int lane = tid & 31;
    const int wid  = tid >> 5;
    const int wm   = wid & 1;        // 0..1: 32-row slice
    const int wn   = wid >> 1;       // 0..3: 32-col slice
    const int n0   = blockIdx.x * BN;
    const int lane15 = lane & 15;
    const int ksel   = (lane >> 4) << 3;

    // Load resident W slice [128 K-rows, 128 cols] + first A chunk
    #pragma unroll
    for (int i = 0; i < 8; i++) {
        int idx = tid + i * 256;      // < 2048
        int r = idx >> 4;             // K-row 0..127
        int q = idx & 15;             // 16 x 16B per 128-half row
        cp16(s_ws + (r * WS_ROW + q * 8) * 2,
             g_Ws + (size_t)r * CTOT + n0 + q * 8, 16);
    }
    load_a_chunk(s_as, blockIdx.y, 0, tid);
    cp_commit();
    cp_wait<0>();
    __syncthreads();

    // Hoist ALL B fragments into registers: Breg[chunk][ks][np][4].
    uint32_t Breg[2][4][2][4];
    #pragma unroll
    for (int cp = 0; cp < 2; cp++)
        #pragma unroll
        for (int ks = 0; ks < 4; ks++)
            #pragma unroll
            for (int np = 0; np < 2; np++) {
                uint32_t addr = s_ws +
                    ((cp * BKC + ks * 16 + lane15) * WS_ROW + wn * 32 + np * 16 + ksel) * 2;
                ldsm_x4_t(Breg[cp][ks][np], addr);
            }

    const bool bias = (n0 < HIDDEN);
    int gc = 0;

    for (int mt = blockIdx.y; mt < NMT; mt += GRID_Y) {
        float acc[2][4][4];
        #pragma unroll
        for (int mi = 0; mi < 2; mi++)
            #pragma unroll
            for (int ni = 0; ni < 4; ni++)
                #pragma unroll
                for (int t = 0; t < 4; t++) acc[mi][ni][t] = 0.0f;

        for (int c = 0; c < NCHUNK; c++, gc++) {
            cp_wait<0>();
            __syncthreads();
            if (c + 1 < NCHUNK) {
                load_a_chunk(s_as + ((gc + 1) & 1) * AS_BUF_BYTES, mt, c + 1, tid);
                cp_commit();
            } else if (mt + GRID_Y < NMT) {
                load_a_chunk(s_as + ((gc + 1) & 1) * AS_BUF_BYTES, mt + GRID_Y, 0, tid);
                cp_commit();
            }
            const uint32_t abuf = s_as + (gc & 1) * AS_BUF_BYTES;
            const int cp = c & 1;
            #pragma unroll
            for (int ks = 0; ks < 4; ks++) {
                uint32_t Af[2][4];
                #pragma unroll
                for (int mi = 0; mi < 2; mi++) {
                    uint32_t addr = abuf +
                        ((wm * 32 + mi * 16 + lane15) * AS_ROW + ks * 16 + ksel) * 2;
                    ldsm_x4(Af[mi], addr);
                }
                #pragma unroll
                for (int mi = 0; mi < 2; mi++)
                    #pragma unroll
                    for (int np = 0; np < 2; np++) {
                        mma16816(acc[mi][np * 2 + 0], Af[mi],
                                 Breg[cp][ks][np][0], Breg[cp][ks][np][1]);
                        mma16816(acc[mi][np * 2 + 1], Af[mi],
                                 Breg[cp][ks][np][2], Breg[cp][ks][np][3]);
                    }
            }
        }

        const int m_base = mt * BM + wm * 32;
        #pragma unroll
        for (int ni = 0; ni < 4; ni++) {
            int col = n0 + wn * 32 + ni * 8 + ((lane & 3) << 1);
            float bb0 = 0.f, bb1 = 0.f;
            if (bias) { bb0 = b1[col]; bb1 = b1[col + 1]; }
            #pragma unroll
            for (int mi = 0; mi < 2; mi++) {
                int r0 = m_base + mi * 16 + (lane >> 2);
                float* a = acc[mi][ni];
                if (r0 < N_NODES)
                    *(__half2*)(g_Ch + (size_t)r0 * CTOT + col) =
                        __floats2half2_rn(a[0] + bb0, a[1] + bb1);
                int r1 = r0 + 8;
                if (r1 < N_NODES)
                    *(__half2*)(g_Ch + (size_t)r1 * CTOT + col) =
                        __floats2half2_rn(a[2] + bb0, a[3] + bb1);
            }
        }
    }
}

// ---------------------------------------------------------------------------
// Edge kernel (UNCHANGED from round 14 winner, protected)
// ---------------------------------------------------------------------------
__global__ void __launch_bounds__(256, 2) edge_kernel(
    const float* __restrict__ polar,
    const void*  __restrict__ srcv,
    const void*  __restrict__ dstv,
    const float* __restrict__ W1,
    const float* __restrict__ gamma,
    const float* __restrict__ beta,
    const float* __restrict__ W2,
    const float* __restrict__ b2,
    float* __restrict__ out)
{
    const int lane = threadIdx.x & 31;
    const int warp = (blockIdx.x * blockDim.x + threadIdx.x) >> 5;
    const int nwarps = (gridDim.x * blockDim.x) >> 5;
    const int j0 = lane * 8;
    const unsigned FULL = 0xFFFFFFFFu;

    float wp0[8], wp1[8], ga[8], be[8], w2a[8], w2b[8];
    #pragma unroll
    for (int i = 0; i < 8; i++) {
        int j = j0 + i;
        wp0[i] = W1[(size_t)128 * HIDDEN + j];
        wp1[i] = W1[(size_t)129 * HIDDEN + j];
        ga[i]  = gamma[j];
        be[i]  = beta[j];
        w2a[i] = W2[j * 2 + 0];
        w2b[i] = W2[j * 2 + 1];
    }
    const float bias0 = b2[0], bias1 = b2[1];
    const float mybias = (lane < 16) ? bias0 : bias1;
    const bool writer = ((lane & 15) == 0);
    const int  wsel   = lane >> 4;

    const bool is64 = (g_idx64 != 0);
    const long long* src64 = (const long long*)srcv;
    const long long* dst64 = (const long long*)dstv;
    const int*       src32 = (const int*)srcv;
    const int*       dst32 = (const int*)dstv;

    for (int e = warp * 4; e < E_EDGES; e += 4 * nwarps) {
        int s[4], d[4];
        if (is64) {
            longlong2 S0 = *(const longlong2*)(src64 + e);
            longlong2 S1 = *(const longlong2*)(src64 + e + 2);
            longlong2 D0 = *(const longlong2*)(dst64 + e);
            longlong2 D1 = *(const longlong2*)(dst64 + e + 2);
            s[0] = (int)S0.x; s[1] = (int)S0.y; s[2] = (int)S1.x; s[3] = (int)S1.y;
            d[0] = (int)D0.x; d[1] = (int)D0.y; d[2] = (int)D1.x; d[3] = (int)D1.y;
        } else {
            int4 S = *(const int4*)(src32 + e);
            int4 D = *(const int4*)(dst32 + e);
            s[0] = S.x; s[1] = S.y; s[2] = S.z; s[3] = S.w;
            d[0] = D.x; d[1] = D.y; d[2] = D.z; d[3] = D.w;
        }
        float4 p01 = *(const float4*)(polar + (size_t)e * 2);
        float4 p23 = *(const float4*)(polar + (size_t)e * 2 + 4);
        float px[4] = {p01.x, p01.z, p23.x, p23.z};
        float py[4] = {p01.y, p01.w, p23.y, p23.w};

        uint4 va[4], vb[4];
        #pragma unroll
        for (int ei = 0; ei < 4; ei++) {
            va[ei] = *(const uint4*)(g_Ch + (size_t)s[ei] * CTOT + j0);
            vb[ei] = *(const uint4*)(g_Ch + (size_t)d[ei] * CTOT + HIDDEN + j0);
        }

        #pragma unroll
        for (int ei = 0; ei < 4; ei++) {
            const __half2* ah = reinterpret_cast<const __half2*>(&va[ei]);
            const __half2* bh = reinterpret_cast<const __half2*>(&vb[ei]);
            float2 zp0 = __half22float2(__hadd2(ah[0], bh[0]));
            float2 zp1 = __half22float2(__hadd2(ah[1], bh[1]));
            float2 zp2 = __half22float2(__hadd2(ah[2], bh[2]));
            float2 zp3 = __half22float2(__hadd2(ah[3], bh[3]));
            float z[8] = {zp0.x, zp0.y, zp1.x, zp1.y, zp2.x, zp2.y, zp3.x, zp3.y};
            #pragma unroll
            for (int i = 0; i < 8; i++)
                z[i] = fmaf(px[ei], wp0[i], fmaf(py[ei], wp1[i], z[i]));

            float s1v = 0.f, s2v = 0.f;
            #pragma unroll
            for (int i = 0; i < 8; i++) {
                s1v += z[i];
                s2v = fmaf(z[i], z[i], s2v);
            }
            s1v += __shfl_xor_sync(FULL, s1v, 16);
            s2v += __shfl_xor_sync(FULL, s2v, 16);
            float ms = (lane < 16) ? s1v : s2v;
            #pragma unroll
            for (int o2 = 8; o2 > 0; o2 >>= 1)
                ms += __shfl_xor_sync(FULL, ms, o2);
            const float s1t = __shfl_sync(FULL, ms, lane & 15);
            const float s2t = __shfl_sync(FULL, ms, (lane & 15) | 16);

            const float mean = s1t * (1.0f / 256.0f);
            const float var  = fmaf(-mean, mean, s2t * (1.0f / 256.0f));
            const float rstd = rsqrtf(var + 1e-5f);
            const float nmr  = -mean * rstd;

            float acc0 = 0.f, acc1 = 0.f;
            #pragma unroll
            for (int i = 0; i < 8; i++) {
                float t = fmaf(z[i], rstd, nmr);
                float y = fmaf(t, ga[i], be[i]);
                y = fmaxf(y, 0.0f);
                acc0 = fmaf(y, w2a[i], acc0);
                acc1 = fmaf(y, w2b[i], acc1);
            }
            acc0 += __shfl_xor_sync(FULL, acc0, 16);
            acc1 += __shfl_xor_sync(FULL, acc1, 16);
            float av = (lane < 16) ? acc0 : acc1;
            #pragma unroll
            for (int o2 = 8; o2 > 0; o2 >>= 1)
                av += __shfl_xor_sync(FULL, av, o2);
            if (writer)
                out[(size_t)(e + ei) * 2 + wsel] = av + mybias;
        }
    }
}

// ---------------------------------------------------------------------------
// Launch
// ---------------------------------------------------------------------------
extern "C" void kernel_launch(void* const* d_in, const int* in_sizes, int n_in,
                              void* d_out, int out_size) {
    const float* h     = (const float*)d_in[0];
    const float* cls   = (const float*)d_in[1];
    const float* polar = (const float*)d_in[2];
    const void*  src   = d_in[3];
    const void*  dst   = d_in[4];
    const float* W1    = (const float*)d_in[5];
    const float* b1    = (const float*)d_in[6];
    const float* gamma = (const float*)d_in[7];
    const float* beta  = (const float*)d_in[8];
    const float* W2    = (const float*)d_in[9];
    const float* b2    = (const float*)d_in[10];
    float* out = (float*)d_out;

    (void)in_sizes; (void)n_in; (void)out_size;

    cudaFuncSetAttribute(node_mma_kernel,
                         cudaFuncAttributeMaxDynamicSharedMemorySize, GEMM_SMEM);

    detect_idx_kernel<<<1, 1>>>(src);

    {
        int total = N_NODES * XDIM;
        prep_x_kernel<<<(total + 255) / 256, 256>>>(h, cls);
    }
    {
        int total = XDIM * CTOT;
        prep_w_kernel<<<(total + 255) / 256, 256>>>(W1);
    }
    {
        dim3 grid(CTOT / BN, GRID_Y);   // (4, 74) = 296 CTAs -> 2 CTAs/SM
        node_mma_kernel<<<grid, 256, GEMM_SMEM>>>(b1);
    }
    {
        edge_kernel<<<1184, 256>>>(polar, src, dst, W1, gamma, beta, W2, b2, out);
    }
}

// round 17
// speedup vs baseline: 1.7984x; 1.0144x over previous
#include <cuda_runtime.h>
#include <cuda_fp16.h>
#include <cstdint>

// Problem constants
#define N_NODES 100000
#define E_EDGES 1000000
#define H_DIMC  124
#define XDIM    128
#define HIDDEN  256
#define CTOT    512     // A (256) || B (256)
#define KSP     128     // single fp16 hi term

// ---------------------------------------------------------------------------
// Static device scratch
// ---------------------------------------------------------------------------
__device__ __half g_Xs[(size_t)N_NODES * KSP];   // [N,128] fp16 = hi(x) (26MB)
__device__ __half g_Ws[(size_t)XDIM * CTOT];     // [128,512] fp16 = hi(Wg)
__device__ __half g_Ch[(size_t)N_NODES * CTOT];  // [N,512] fp16 = [A|B], b1 folded into A
__device__ int    g_idx64;

// ---------------------------------------------------------------------------
// PTX helpers
// ---------------------------------------------------------------------------
__device__ __forceinline__ uint32_t smem_u32(const void* p) {
    return (uint32_t)__cvta_generic_to_shared(p);
}
__device__ __forceinline__ void ldsm_x4(uint32_t (&r)[4], uint32_t addr) {
    asm volatile("ldmatrix.sync.aligned.m8n8.x4.shared.b16 {%0,%1,%2,%3}, [%4];"
                 : "=r"(r[0]), "=r"(r[1]), "=r"(r[2]), "=r"(r[3]) : "r"(addr));
}
__device__ __forceinline__ void ldsm_x4_t(uint32_t* r, uint32_t addr) {
    asm volatile("ldmatrix.sync.aligned.m8n8.x4.trans.shared.b16 {%0,%1,%2,%3}, [%4];"
                 : "=r"(r[0]), "=r"(r[1]), "=r"(r[2]), "=r"(r[3]) : "r"(addr));
}
__device__ __forceinline__ void mma16816(float (&d)[4], const uint32_t (&a)[4],
                                         uint32_t b0, uint32_t b1) {
    asm volatile("mma.sync.aligned.m16n8k16.row.col.f32.f16.f16.f32 "
                 "{%0,%1,%2,%3}, {%4,%5,%6,%7}, {%8,%9}, {%0,%1,%2,%3};"
                 : "+f"(d[0]), "+f"(d[1]), "+f"(d[2]), "+f"(d[3])
                 : "r"(a[0]), "r"(a[1]), "r"(a[2]), "r"(a[3]), "r"(b0), "r"(b1));
}
__device__ __forceinline__ void cp16(uint32_t dst, const void* src, int sz) {
    asm volatile("cp.async.cg.shared.global [%0], [%1], 16, %2;"
                 :: "r"(dst), "l"(src), "r"(sz));
}
__device__ __forceinline__ void cp_commit() { asm volatile("cp.async.commit_group;"); }
template <int K>
__device__ __forceinline__ void cp_wait() { asm volatile("cp.async.wait_group %0;" :: "n"(K)); }

// ---------------------------------------------------------------------------
// Fused prep: detect idx width + pack Ws + pack Xs (one launch)
// ---------------------------------------------------------------------------
__global__ void prep_all_kernel(const float* __restrict__ h,
                                const float* __restrict__ cls,
                                const float* __restrict__ W1,
                                const void*  __restrict__ srcv) {
    int idx = blockIdx.x * blockDim.x + threadIdx.x;

    if (idx == 0) {
        const unsigned long long* p = (const unsigned long long*)srcv;
        int ok = 1;
        #pragma unroll
        for (int i = 0; i < 8; i++)
            if (p[i] >= (unsigned long long)N_NODES) ok = 0;
        g_idx64 = ok;
    }

    if (idx < XDIM * CTOT) {
        int k = idx >> 9;
        int c = idx & 511;
        float w = (c < HIDDEN) ? W1[(size_t)k * HIDDEN + c]
                               : W1[(size_t)(130 + k) * HIDDEN + (c - HIDDEN)];
        g_Ws[(size_t)k * CTOT + c] = __float2half_rn(w);
    }

    if (idx >= N_NODES * XDIM) return;
    int n = idx >> 7;
    int j = idx & 127;
    float v;
    if (j < H_DIMC) {
        v = h[(size_t)n * H_DIMC + j];
    } else {
        int c = j - H_DIMC;
        float4 l = *(const float4*)(cls + (size_t)n * 4);
        float m = fmaxf(fmaxf(l.x, l.y), fmaxf(l.z, l.w));
        float e0 = expf(l.x - m), e1 = expf(l.y - m);
        float e2 = expf(l.z - m), e3 = expf(l.w - m);
        float inv = 1.0f / (e0 + e1 + e2 + e3);
        float ec = (c == 0) ? e0 : (c == 1) ? e1 : (c == 2) ? e2 : e3;
        v = ec * inv;
    }
    g_Xs[(size_t)n * KSP + j] = __float2half_rn(v);
}

// ---------------------------------------------------------------------------
// Tensor-core node GEMM (UNCHANGED from round 15: 54.5us, protected)
// ---------------------------------------------------------------------------
#define BM 64
#define BN 128
#define BKC 64
#define NCHUNK (KSP / BKC)               // 2
#define WS_ROW 136
#define AS_ROW 72
#define WS_BYTES (128 * WS_ROW * 2)       // 34816
#define AS_BUF_BYTES (BM * AS_ROW * 2)    // 9216
#define GEMM_SMEM (WS_BYTES + 2 * AS_BUF_BYTES)  // 53248
#define NMT ((N_NODES + BM - 1) / BM)     // 1563
#define GRID_Y 74

__device__ __forceinline__ void load_a_chunk(uint32_t s_as, int mt, int c, int tid) {
    #pragma unroll
    for (int i = 0; i < 2; i++) {
        int idx = tid + i * 256;         // 0..511
        int r = idx >> 3;                // 0..63
        int q = idx & 7;                 // 8 x 16B per 64-half row
        int m = mt * BM + r;
        const __half* src = g_Xs + (size_t)(m < N_NODES ? m : 0) * KSP + c * BKC + q * 8;
        cp16(s_as + (r * AS_ROW + q * 8) * 2, src, (m < N_NODES) ? 16 : 0);
    }
}

__global__ void __launch_bounds__(256, 2) node_mma_kernel(const float* __restrict__ b1) {
    extern __shared__ char smem[];
    const uint32_t s_ws = smem_u32(smem);
    const uint32_t s_as = s_ws + WS_BYTES;

    const int tid  = threadIdx.x;
    const int lane = tid & 31;
    const int wid  = tid >> 5;
    const int wm   = wid & 1;
    const int wn   = wid >> 1;
    const int n0   = blockIdx.x * BN;
    const int lane15 = lane & 15;
    const int ksel   = (lane >> 4) << 3;

    #pragma unroll
    for (int i = 0; i < 8; i++) {
        int idx = tid + i * 256;
        int r = idx >> 4;
        int q = idx & 15;
        cp16(s_ws + (r * WS_ROW + q * 8) * 2,
             g_Ws + (size_t)r * CTOT + n0 + q * 8, 16);
    }
    load_a_chunk(s_as, blockIdx.y, 0, tid);
    cp_commit();
    cp_wait<0>();
    __syncthreads();

    uint32_t Breg[2][4][2][4];
    #pragma unroll
    for (int cp = 0; cp < 2; cp++)
        #pragma unroll
        for (int ks = 0; ks < 4; ks++)
            #pragma unroll
            for (int np = 0; np < 2; np++) {
                uint32_t addr = s_ws +
                    ((cp * BKC + ks * 16 + lane15) * WS_ROW + wn * 32 + np * 16 + ksel) * 2;
                ldsm_x4_t(Breg[cp][ks][np], addr);
            }

    const bool bias = (n0 < HIDDEN);
    int gc = 0;

    for (int mt = blockIdx.y; mt < NMT; mt += GRID_Y) {
        float acc[2][4][4];
        #pragma unroll
        for (int mi = 0; mi < 2; mi++)
            #pragma unroll
            for (int ni = 0; ni < 4; ni++)
                #pragma unroll
                for (int t = 0; t < 4; t++) acc[mi][ni][t] = 0.0f;

        for (int c = 0; c < NCHUNK; c++, gc++) {
            cp_wait<0>();
            __syncthreads();
            if (c + 1 < NCHUNK) {
                load_a_chunk(s_as + ((gc + 1) & 1) * AS_BUF_BYTES, mt, c + 1, tid);
                cp_commit();
            } else if (mt + GRID_Y < NMT) {
                load_a_chunk(s_as + ((gc + 1) & 1) * AS_BUF_BYTES, mt + GRID_Y, 0, tid);
                cp_commit();
            }
            const uint32_t abuf = s_as + (gc & 1) * AS_BUF_BYTES;
            const int cp = c & 1;
            #pragma unroll
            for (int ks = 0; ks < 4; ks++) {
                uint32_t Af[2][4];
                #pragma unroll
                for (int mi = 0; mi < 2; mi++) {
                    uint32_t addr = abuf +
                        ((wm * 32 + mi * 16 + lane15) * AS_ROW + ks * 16 + ksel) * 2;
                    ldsm_x4(Af[mi], addr);
                }
                #pragma unroll
                for (int mi = 0; mi < 2; mi++)
                    #pragma unroll
                    for (int np = 0; np < 2; np++) {
                        mma16816(acc[mi][np * 2 + 0], Af[mi],
                                 Breg[cp][ks][np][0], Breg[cp][ks][np][1]);
                        mma16816(acc[mi][np * 2 + 1], Af[mi],
                                 Breg[cp][ks][np][2], Breg[cp][ks][np][3]);
                    }
            }
        }

        const int m_base = mt * BM + wm * 32;
        #pragma unroll
        for (int ni = 0; ni < 4; ni++) {
            int col = n0 + wn * 32 + ni * 8 + ((lane & 3) << 1);
            float bb0 = 0.f, bb1 = 0.f;
            if (bias) { bb0 = b1[col]; bb1 = b1[col + 1]; }
            #pragma unroll
            for (int mi = 0; mi < 2; mi++) {
                int r0 = m_base + mi * 16 + (lane >> 2);
                float* a = acc[mi][ni];
                if (r0 < N_NODES)
                    *(__half2*)(g_Ch + (size_t)r0 * CTOT + col) =
                        __floats2half2_rn(a[0] + bb0, a[1] + bb1);
                int r1 = r0 + 8;
                if (r1 < N_NODES)
                    *(__half2*)(g_Ch + (size_t)r1 * CTOT + col) =
                        __floats2half2_rn(a[2] + bb0, a[3] + bb1);
            }
        }
    }
}

// ---------------------------------------------------------------------------
// Edge kernel: register-gather, 4 edges/warp-iter, paired shfl reductions,
// predicated direct stores (round-15 proven form, ~225us).
// ---------------------------------------------------------------------------
__global__ void __launch_bounds__(256, 2) edge_kernel(
    const float* __restrict__ polar,
    const void*  __restrict__ srcv,
    const void*  __restrict__ dstv,
    const float* __restrict__ W1,
    const float* __restrict__ gamma,
    const float* __restrict__ beta,
    const float* __restrict__ W2,
    const float* __restrict__ b2,
    float* __restrict__ out)
{
    const int lane = threadIdx.x & 31;
    const int warp = (blockIdx.x * blockDim.x + threadIdx.x) >> 5;
    const int nwarps = (gridDim.x * blockDim.x) >> 5;
    const int j0 = lane * 8;
    const unsigned FULL = 0xFFFFFFFFu;

    float wp0[8], wp1[8], ga[8], be[8], w2a[8], w2b[8];
    #pragma unroll
    for (int i = 0; i < 8; i++) {
        int j = j0 + i;
        wp0[i] = W1[(size_t)128 * HIDDEN + j];
        wp1[i] = W1[(size_t)129 * HIDDEN + j];
        ga[i]  = gamma[j];
        be[i]  = beta[j];
        w2a[i] = W2[j * 2 + 0];
        w2b[i] = W2[j * 2 + 1];
    }
    const float bias0 = b2[0], bias1 = b2[1];
    const float mybias = (lane < 16) ? bias0 : bias1;
    const bool writer = ((lane & 15) == 0);
    const int  wsel   = lane >> 4;

    const bool is64 = (g_idx64 != 0);
    const long long* src64 = (const long long*)srcv;
    const long long* dst64 = (const long long*)dstv;
    const int*       src32 = (const int*)srcv;
    const int*       dst32 = (const int*)dstv;

    for (int e = warp * 4; e < E_EDGES; e += 4 * nwarps) {
        int s[4], d[4];
        if (is64) {
            longlong2 S0 = *(const longlong2*)(src64 + e);
            longlong2 S1 = *(const longlong2*)(src64 + e + 2);
            longlong2 D0 = *(const longlong2*)(dst64 + e);
            longlong2 D1 = *(const longlong2*)(dst64 + e + 2);
            s[0] = (int)S0.x; s[1] = (int)S0.y; s[2] = (int)S1.x; s[3] = (int)S1.y;
            d[0] = (int)D0.x; d[1] = (int)D0.y; d[2] = (int)D1.x; d[3] = (int)D1.y;
        } else {
            int4 S = *(const int4*)(src32 + e);
            int4 D = *(const int4*)(dst32 + e);
            s[0] = S.x; s[1] = S.y; s[2] = S.z; s[3] = S.w;
            d[0] = D.x; d[1] = D.y; d[2] = D.z; d[3] = D.w;
        }
        float4 p01 = *(const float4*)(polar + (size_t)e * 2);
        float4 p23 = *(const float4*)(polar + (size_t)e * 2 + 4);
        float px[4] = {p01.x, p01.z, p23.x, p23.z};
        float py[4] = {p01.y, p01.w, p23.y, p23.w};

        uint4 va[4], vb[4];
        #pragma unroll
        for (int ei = 0; ei < 4; ei++) {
            va[ei] = *(const uint4*)(g_Ch + (size_t)s[ei] * CTOT + j0);
            vb[ei] = *(const uint4*)(g_Ch + (size_t)d[ei] * CTOT + HIDDEN + j0);
        }

        #pragma unroll
        for (int ei = 0; ei < 4; ei++) {
            const __half2* ah = reinterpret_cast<const __half2*>(&va[ei]);
            const __half2* bh = reinterpret_cast<const __half2*>(&vb[ei]);
            float2 zp0 = __half22float2(__hadd2(ah[0], bh[0]));
            float2 zp1 = __half22float2(__hadd2(ah[1], bh[1]));
            float2 zp2 = __half22float2(__hadd2(ah[2], bh[2]));
            float2 zp3 = __half22float2(__hadd2(ah[3], bh[3]));
            float z[8] = {zp0.x, zp0.y, zp1.x, zp1.y, zp2.x, zp2.y, zp3.x, zp3.y};
            #pragma unroll
            for (int i = 0; i < 8; i++)
                z[i] = fmaf(px[ei], wp0[i], fmaf(py[ei], wp1[i], z[i]));

            float s1v = 0.f, s2v = 0.f;
            #pragma unroll
            for (int i = 0; i < 8; i++) {
                s1v += z[i];
                s2v = fmaf(z[i], z[i], s2v);
            }
            s1v += __shfl_xor_sync(FULL, s1v, 16);
            s2v += __shfl_xor_sync(FULL, s2v, 16);
            float ms = (lane < 16) ? s1v : s2v;
            #pragma unroll
            for (int o2 = 8; o2 > 0; o2 >>= 1)
                ms += __shfl_xor_sync(FULL, ms, o2);
            const float s1t = __shfl_sync(FULL, ms, lane & 15);
            const float s2t = __shfl_sync(FULL, ms, (lane & 15) | 16);

            const float mean = s1t * (1.0f / 256.0f);
            const float var  = fmaf(-mean, mean, s2t * (1.0f / 256.0f));
            const float rstd = rsqrtf(var + 1e-5f);
            const float nmr  = -mean * rstd;

            float acc0 = 0.f, acc1 = 0.f;
            #pragma unroll
            for (int i = 0; i < 8; i++) {
                float t = fmaf(z[i], rstd, nmr);
                float y = fmaf(t, ga[i], be[i]);
                y = fmaxf(y, 0.0f);
                acc0 = fmaf(y, w2a[i], acc0);
                acc1 = fmaf(y, w2b[i], acc1);
            }
            acc0 += __shfl_xor_sync(FULL, acc0, 16);
            acc1 += __shfl_xor_sync(FULL, acc1, 16);
            float av = (lane < 16) ? acc0 : acc1;
            #pragma unroll
            for (int o2 = 8; o2 > 0; o2 >>= 1)
                av += __shfl_xor_sync(FULL, av, o2);
            if (writer)
                out[(size_t)(e + ei) * 2 + wsel] = av + mybias;
        }
    }
}

// ---------------------------------------------------------------------------
// Launch
// ---------------------------------------------------------------------------
extern "C" void kernel_launch(void* const* d_in, const int* in_sizes, int n_in,
                              void* d_out, int out_size) {
    const float* h     = (const float*)d_in[0];
    const float* cls   = (const float*)d_in[1];
    const float* polar = (const float*)d_in[2];
    const void*  src   = d_in[3];
    const void*  dst   = d_in[4];
    const float* W1    = (const float*)d_in[5];
    const float* b1    = (const float*)d_in[6];
    const float* gamma = (const float*)d_in[7];
    const float* beta  = (const float*)d_in[8];
    const float* W2    = (const float*)d_in[9];
    const float* b2    = (const float*)d_in[10];
    float* out = (float*)d_out;

    (void)in_sizes; (void)n_in; (void)out_size;

    cudaFuncSetAttribute(node_mma_kernel,
                         cudaFuncAttributeMaxDynamicSharedMemorySize, GEMM_SMEM);

    {
        int total = N_NODES * XDIM;   // covers X pack (12.8M); W pack + detect nested inside
        prep_all_kernel<<<(total + 255) / 256, 256>>>(h, cls, W1, src);
    }
    {
        dim3 grid(CTOT / BN, GRID_Y);   // (4, 74) = 296 CTAs -> 2 CTAs/SM
        node_mma_kernel<<<grid, 256, GEMM_SMEM>>>(b1);
    }
    {
        edge_kernel<<<1184, 256>>>(polar, src, dst, W1, gamma, beta, W2, b2, out);
    }
}